// round 1
// baseline (speedup 1.0000x reference)
#include <cuda_runtime.h>
#include <math.h>

#define Bv 256
#define Nv 128
#define Dv 512
#define BNv (Bv*Nv)

// ---------------- device scratch (no allocations allowed) ----------------
__device__ float g_H[(size_t)BNv*Dv];   // 64 MB, reused for t-head H, s-head H, and U
__device__ float g_mask[BNv];
__device__ float g_cnt[Bv];
__device__ float g_part_t[BNv];
__device__ float g_part_s[BNv];
__device__ float g_part_c[Bv];
__device__ int   g_mfmt;

// ---------------- helpers ----------------
__device__ __forceinline__ float blockReduceSum256(float v, float* sh){
    int tid = threadIdx.x;
    #pragma unroll
    for(int o=16;o>0;o>>=1) v += __shfl_down_sync(0xffffffffu, v, o);
    if((tid&31)==0) sh[tid>>5] = v;
    __syncthreads();
    if(tid<8){
        v = sh[tid];
        #pragma unroll
        for(int o=4;o>0;o>>=1) v += __shfl_down_sync(0xffu, v, o);
        if(tid==0) sh[0] = v;
    }
    __syncthreads();
    float r = sh[0];
    __syncthreads();
    return r;
}

__device__ __forceinline__ float gelu_exact(float x){
    return 0.5f*x*(1.0f + erff(x*0.70710678118654752f));
}

// ---------------- mask format detection / expansion ----------------
// Reads only first 8192 uints (32KB) — valid under int32/float32/uint8 hypotheses.
__global__ void k_detect(const unsigned int* __restrict__ raw){
    __shared__ int f[2];
    if(threadIdx.x==0){ f[0]=1; f[1]=1; }
    __syncthreads();
    for(int i=threadIdx.x;i<8192;i+=256){
        unsigned v = raw[i];
        if(v>1u) f[0]=0;
        if(v!=0u && v!=0x3F800000u) f[1]=0;
    }
    __syncthreads();
    if(threadIdx.x==0) g_mfmt = f[0] ? 0 : (f[1] ? 1 : 2);
}

__global__ void k_expand_mask(const void* __restrict__ raw){
    int i = blockIdx.x*blockDim.x + threadIdx.x;
    if(i>=BNv) return;
    int fmt = g_mfmt;
    float m;
    if(fmt==0)      m = (((const int*)raw)[i]   != 0)    ? 1.f : 0.f;
    else if(fmt==1) m = (((const float*)raw)[i] != 0.f)  ? 1.f : 0.f;
    else            m = (((const unsigned char*)raw)[i]!=0) ? 1.f : 0.f;
    g_mask[i] = m;
}

__global__ void k_cnt(){
    int b = blockIdx.x, tid = threadIdx.x;  // 128 threads
    float v = g_mask[b*Nv + tid];
    #pragma unroll
    for(int o=16;o>0;o>>=1) v += __shfl_down_sync(0xffffffffu, v, o);
    __shared__ float sh[4];
    if((tid&31)==0) sh[tid>>5] = v;
    __syncthreads();
    if(tid==0) g_cnt[b] = sh[0]+sh[1]+sh[2]+sh[3];
}

// ---------------- big GEMM: g_H = act(A[BN,512] @ W[512,512] + bias) ----------------
// 128x128 tile, BK=8, 256 threads, 8x8 micro-tile.
template<int ACT>
__global__ void __launch_bounds__(256) k_gemm(const float* __restrict__ A,
                                              const float* __restrict__ W,
                                              const float* __restrict__ bias){
    __shared__ float As[8][128];
    __shared__ float Bs[8][128];
    int tid = threadIdx.x;
    int tx = tid & 15, ty = tid >> 4;
    int nb = blockIdx.x, mb = blockIdx.y;
    const float* Ab = A + (size_t)mb*128*Dv;
    int n0 = nb*128;
    float acc[8][8];
    #pragma unroll
    for(int i=0;i<8;i++)
        #pragma unroll
        for(int j=0;j<8;j++) acc[i][j] = 0.f;
    int arow = tid>>1,  aoff = (tid&1)*4;
    int brow = tid>>5,  bcol = (tid&31)*4;
    for(int k0=0;k0<Dv;k0+=8){
        float4 a = *reinterpret_cast<const float4*>(&Ab[(size_t)arow*Dv + k0 + aoff]);
        As[aoff+0][arow]=a.x; As[aoff+1][arow]=a.y;
        As[aoff+2][arow]=a.z; As[aoff+3][arow]=a.w;
        float4 w = *reinterpret_cast<const float4*>(&W[(size_t)(k0+brow)*Dv + n0 + bcol]);
        *reinterpret_cast<float4*>(&Bs[brow][bcol]) = w;
        __syncthreads();
        #pragma unroll
        for(int k=0;k<8;k++){
            float ra[8], rb[8];
            #pragma unroll
            for(int i=0;i<8;i++) ra[i] = As[k][ty*8+i];
            #pragma unroll
            for(int j=0;j<8;j++) rb[j] = Bs[k][tx*8+j];
            #pragma unroll
            for(int i=0;i<8;i++)
                #pragma unroll
                for(int j=0;j<8;j++) acc[i][j] = fmaf(ra[i], rb[j], acc[i][j]);
        }
        __syncthreads();
    }
    #pragma unroll
    for(int i=0;i<8;i++){
        size_t m = (size_t)mb*128 + ty*8 + i;
        #pragma unroll
        for(int j4=0;j4<2;j4++){
            float4 v;
            float* vp = &v.x;
            #pragma unroll
            for(int q=0;q<4;q++){
                int j = j4*4+q;
                int n = n0 + tx*8 + j;
                float c = acc[i][j];
                if(bias) c += bias[n];
                if(ACT==1) c = gelu_exact(c);
                vp[q] = c;
            }
            *reinterpret_cast<float4*>(&g_H[m*Dv + n0 + tx*8 + j4*4]) = v;
        }
    }
}

// ---------------- type head: LN + W2[512,6] + masked CE ----------------
__global__ void __launch_bounds__(256) k_type(const float* __restrict__ W2,
                                              const float* __restrict__ b2,
                                              const float* __restrict__ gam,
                                              const float* __restrict__ bet,
                                              const int* __restrict__ tgt){
    __shared__ float sh[8];
    int row = blockIdx.x, tid = threadIdx.x;
    const float* h = g_H + (size_t)row*Dv;
    float x0 = h[tid], x1 = h[tid+256];
    float mu  = blockReduceSum256(x0+x1, sh) * (1.f/Dv);
    float d0 = x0-mu, d1 = x1-mu;
    float var = blockReduceSum256(d0*d0 + d1*d1, sh) * (1.f/Dv);
    float rs = rsqrtf(var + 1e-5f);
    float y0 = d0*rs*gam[tid]     + bet[tid];
    float y1 = d1*rs*gam[tid+256] + bet[tid+256];
    float lg[6];
    #pragma unroll
    for(int c=0;c<6;c++){
        float p = y0*W2[tid*6+c] + y1*W2[(tid+256)*6+c];
        lg[c] = blockReduceSum256(p, sh);
    }
    if(tid==0){
        float mx = -1e30f;
        #pragma unroll
        for(int c=0;c<6;c++){ lg[c] += b2[c]; mx = fmaxf(mx, lg[c]); }
        float se = 0.f;
        #pragma unroll
        for(int c=0;c<6;c++) se += expf(lg[c]-mx);
        float lse = mx + logf(se);
        int t = tgt[row & (Nv-1)];
        g_part_t[row] = g_mask[row] * (lse - lg[t]);
    }
}

// ---------------- stats head: LN + W2[512,8] + masked MSE ----------------
__global__ void __launch_bounds__(256) k_stats(const float* __restrict__ W2,
                                               const float* __restrict__ b2,
                                               const float* __restrict__ gam,
                                               const float* __restrict__ bet,
                                               const float* __restrict__ st){
    __shared__ float sh[8];
    int row = blockIdx.x, tid = threadIdx.x;
    const float* h = g_H + (size_t)row*Dv;
    float x0 = h[tid], x1 = h[tid+256];
    float mu  = blockReduceSum256(x0+x1, sh) * (1.f/Dv);
    float d0 = x0-mu, d1 = x1-mu;
    float var = blockReduceSum256(d0*d0 + d1*d1, sh) * (1.f/Dv);
    float rs = rsqrtf(var + 1e-5f);
    float y0 = d0*rs*gam[tid]     + bet[tid];
    float y1 = d1*rs*gam[tid+256] + bet[tid+256];
    float pr[8];
    #pragma unroll
    for(int c=0;c<8;c++){
        float p = y0*W2[tid*8+c] + y1*W2[(tid+256)*8+c];
        pr[c] = blockReduceSum256(p, sh);
    }
    if(tid==0){
        float s = 0.f;
        #pragma unroll
        for(int c=0;c<8;c++){
            float d = pr[c] + b2[c] - st[(size_t)row*8 + c];
            s += d*d;
        }
        g_part_s[row] = g_mask[row] * s;
    }
}

// ---------------- correlation: per batch S = U @ E^T, tanh, diag=1, masked SE ----------------
__global__ void __launch_bounds__(256) k_corr(const float* __restrict__ E,
                                              const float* __restrict__ corr_t,
                                              const float* __restrict__ cb_ptr){
    __shared__ float Us[8][128];
    __shared__ float Es[8][128];
    __shared__ float sh[8];
    int b = blockIdx.x, tid = threadIdx.x;
    int tx = tid & 15, ty = tid >> 4;
    const float* U  = g_H + (size_t)b*Nv*Dv;
    const float* Eb = E   + (size_t)b*Nv*Dv;
    float acc[8][8];
    #pragma unroll
    for(int i=0;i<8;i++)
        #pragma unroll
        for(int j=0;j<8;j++) acc[i][j] = 0.f;
    int row = tid>>1, off = (tid&1)*4;
    for(int k0=0;k0<Dv;k0+=8){
        float4 a = *reinterpret_cast<const float4*>(&U [(size_t)row*Dv + k0 + off]);
        Us[off+0][row]=a.x; Us[off+1][row]=a.y; Us[off+2][row]=a.z; Us[off+3][row]=a.w;
        float4 e = *reinterpret_cast<const float4*>(&Eb[(size_t)row*Dv + k0 + off]);
        Es[off+0][row]=e.x; Es[off+1][row]=e.y; Es[off+2][row]=e.z; Es[off+3][row]=e.w;
        __syncthreads();
        #pragma unroll
        for(int k=0;k<8;k++){
            float ra[8], rb[8];
            #pragma unroll
            for(int i=0;i<8;i++) ra[i] = Us[k][ty*8+i];
            #pragma unroll
            for(int j=0;j<8;j++) rb[j] = Es[k][tx*8+j];
            #pragma unroll
            for(int i=0;i<8;i++)
                #pragma unroll
                for(int j=0;j<8;j++) acc[i][j] = fmaf(ra[i], rb[j], acc[i][j]);
        }
        __syncthreads();
    }
    float cb = *cb_ptr;
    float local = 0.f;
    #pragma unroll
    for(int i=0;i<8;i++){
        int gi = ty*8 + i;
        float mi = g_mask[b*Nv + gi];
        #pragma unroll
        for(int j=0;j<8;j++){
            int gj = tx*8 + j;
            float s = tanhf(acc[i][j] + cb);
            if(gi==gj) s = 1.f;
            float d = s - corr_t[(size_t)b*Nv*Nv + (size_t)gi*Nv + gj];
            float me = fmaxf(mi, g_mask[b*Nv + gj]);
            local += me*d*d;
        }
    }
    float tot = blockReduceSum256(local, sh);
    if(tid==0) g_part_c[b] = tot;
}

// ---------------- final deterministic combine ----------------
__global__ void k_final(float* __restrict__ out){
    __shared__ double sh[1024];
    int tid = threadIdx.x;
    double tsum=0, ssum=0, csum=0, nm=0, nme=0;
    for(int i=tid;i<BNv;i+=1024){ tsum += (double)g_part_t[i]; ssum += (double)g_part_s[i]; }
    for(int i=tid;i<Bv;i+=1024){
        csum += (double)g_part_c[i];
        double cnt = (double)g_cnt[i];
        nm += cnt;
        double u = (double)Nv - cnt;
        nme += (double)Nv*(double)Nv - u*u;
    }
    double vals[5] = {tsum, ssum, csum, nm, nme};
    for(int v=0;v<5;v++){
        sh[tid] = vals[v]; __syncthreads();
        for(int o=512;o>0;o>>=1){ if(tid<o) sh[tid]+=sh[tid+o]; __syncthreads(); }
        vals[v] = sh[0]; __syncthreads();
    }
    if(tid==0){
        double nm_  = vals[3] < 1.0 ? 1.0 : vals[3];
        double nme_ = vals[4] < 1.0 ? 1.0 : vals[4];
        double total = vals[0]/nm_ + vals[1]/(nm_*8.0) + 0.5*vals[2]/nme_;
        out[0] = (float)total;
    }
}

// ---------------- launch ----------------
extern "C" void kernel_launch(void* const* d_in, const int* in_sizes, int n_in,
                              void* d_out, int out_size){
    const float* e     = (const float*)d_in[0];
    const void*  mraw  = d_in[1];
    const int*   tgt   = (const int*)d_in[2];
    const float* stats = (const float*)d_in[3];
    const float* corr  = (const float*)d_in[4];
    const float* tW1  = (const float*)d_in[5];
    const float* tb1  = (const float*)d_in[6];
    const float* tg   = (const float*)d_in[7];
    const float* tbe  = (const float*)d_in[8];
    const float* tW2  = (const float*)d_in[9];
    const float* tb2  = (const float*)d_in[10];
    const float* sW1  = (const float*)d_in[11];
    const float* sb1  = (const float*)d_in[12];
    const float* sg   = (const float*)d_in[13];
    const float* sbe  = (const float*)d_in[14];
    const float* sW2  = (const float*)d_in[15];
    const float* sb2  = (const float*)d_in[16];
    const float* cW   = (const float*)d_in[17];
    const float* cb   = (const float*)d_in[18];

    k_detect<<<1,256>>>((const unsigned int*)mraw);
    k_expand_mask<<<BNv/256,256>>>(mraw);
    k_cnt<<<Bv,128>>>();

    dim3 gg(Dv/128, BNv/128);   // (4, 256)

    // type head
    k_gemm<1><<<gg,256>>>(e, tW1, tb1);
    k_type<<<BNv,256>>>(tW2, tb2, tg, tbe, tgt);

    // stats head
    k_gemm<1><<<gg,256>>>(e, sW1, sb1);
    k_stats<<<BNv,256>>>(sW2, sb2, sg, sbe, stats);

    // correlation: U = e @ c_W (no bias/act), then batched bilinear
    k_gemm<0><<<gg,256>>>(e, cW, nullptr);
    k_corr<<<Bv,256>>>(e, corr, cb);

    k_final<<<1,1024>>>((float*)d_out);
}

// round 3
// speedup vs baseline: 1.9809x; 1.9809x over previous
#include <cuda_runtime.h>
#include <math.h>
#include <stdint.h>

#define Bv 256
#define Nv 128
#define Dv 512
#define BNv (Bv*Nv)

// ---------------- device scratch ----------------
__device__ float g_H[(size_t)BNv*Dv];   // 64 MB: H for heads / U for corr
__device__ float g_WT[Dv*Dv];           // transposed weight staging
__device__ float g_mask[BNv];
__device__ float g_cnt[Bv];
__device__ float g_part_t[BNv];
__device__ float g_part_s[BNv];
__device__ float g_part_c[Bv];
__device__ int   g_mfmt;

// ---------------- helpers ----------------
__device__ __forceinline__ uint32_t s2u(const void* p){
    uint32_t a;
    asm("{ .reg .u64 t; cvta.to.shared.u64 t, %1; cvt.u32.u64 %0, t; }":"=r"(a):"l"(p));
    return a;
}
__device__ __forceinline__ uint32_t f2tf(float x){
    uint32_t r; asm("cvt.rna.tf32.f32 %0, %1;":"=r"(r):"f"(x)); return r;
}
__device__ __forceinline__ void mma_tf32(float* d, const uint32_t* a, uint32_t b0, uint32_t b1){
    asm volatile(
      "mma.sync.aligned.m16n8k8.row.col.f32.tf32.tf32.f32 "
      "{%0,%1,%2,%3}, {%4,%5,%6,%7}, {%8,%9}, {%0,%1,%2,%3};"
      : "+f"(d[0]),"+f"(d[1]),"+f"(d[2]),"+f"(d[3])
      : "r"(a[0]),"r"(a[1]),"r"(a[2]),"r"(a[3]), "r"(b0),"r"(b1));
}
__device__ __forceinline__ float blockReduceSum256(float v, float* sh){
    int tid = threadIdx.x;
    #pragma unroll
    for(int o=16;o>0;o>>=1) v += __shfl_down_sync(0xffffffffu, v, o);
    if((tid&31)==0) sh[tid>>5] = v;
    __syncthreads();
    if(tid<8){
        v = sh[tid];
        #pragma unroll
        for(int o=4;o>0;o>>=1) v += __shfl_down_sync(0xffu, v, o);
        if(tid==0) sh[0] = v;
    }
    __syncthreads();
    float r = sh[0];
    __syncthreads();
    return r;
}
__device__ __forceinline__ float gelu_exact(float x){
    return 0.5f*x*(1.0f + erff(x*0.70710678118654752f));
}

// ---------------- mask format detection / expansion ----------------
__global__ void k_detect(const unsigned int* __restrict__ raw){
    __shared__ int f[2];
    if(threadIdx.x==0){ f[0]=1; f[1]=1; }
    __syncthreads();
    for(int i=threadIdx.x;i<8192;i+=256){
        unsigned v = raw[i];
        if(v>1u) f[0]=0;
        if(v!=0u && v!=0x3F800000u) f[1]=0;
    }
    __syncthreads();
    if(threadIdx.x==0) g_mfmt = f[0] ? 0 : (f[1] ? 1 : 2);
}
__global__ void k_expand_mask(const void* __restrict__ raw){
    int i = blockIdx.x*blockDim.x + threadIdx.x;
    if(i>=BNv) return;
    int fmt = g_mfmt;
    float m;
    if(fmt==0)      m = (((const int*)raw)[i]   != 0)    ? 1.f : 0.f;
    else if(fmt==1) m = (((const float*)raw)[i] != 0.f)  ? 1.f : 0.f;
    else            m = (((const unsigned char*)raw)[i]!=0) ? 1.f : 0.f;
    g_mask[i] = m;
}
__global__ void k_cnt(){
    int b = blockIdx.x, tid = threadIdx.x;
    float v = g_mask[b*Nv + tid];
    #pragma unroll
    for(int o=16;o>0;o>>=1) v += __shfl_down_sync(0xffffffffu, v, o);
    __shared__ float sh[4];
    if((tid&31)==0) sh[tid>>5] = v;
    __syncthreads();
    if(tid==0) g_cnt[b] = sh[0]+sh[1]+sh[2]+sh[3];
}

// ---------------- weight transpose: g_WT[n][k] = W[k][n] ----------------
__global__ void k_transpose(const float* __restrict__ W){
    __shared__ float t[32][33];
    int bx = blockIdx.x*32, by = blockIdx.y*32;
    int x = threadIdx.x, y = threadIdx.y;   // (32,8)
    #pragma unroll
    for(int i=0;i<32;i+=8) t[y+i][x] = W[(size_t)(by+y+i)*Dv + bx+x];
    __syncthreads();
    #pragma unroll
    for(int i=0;i<32;i+=8) g_WT[(size_t)(bx+y+i)*Dv + by+x] = t[x][y+i];
}

// ---------------- tf32 mma.sync GEMM: g_H = act(A @ W + bias) ----------------
// A [BN,512] row-major; B = g_WT [n][k] K-major.
// CTA: 128x128 tile, 16 K-chunks of 32, cp.async double buffer.
// SMEM layouts stride-36: bank(row,k) = (4*row+k)%32 -> conflict-free frags.
#define KC 32
#define NCHUNK 16
#define AS_STRIDE 36
#define ABUF_FLOATS (128*AS_STRIDE)            // 4608
#define BUF_FLOATS  (2*ABUF_FLOATS)            // 9216 (A then B)
#define SMEM_SZ     (BUF_FLOATS*2*4)           // 73728 bytes

template<int ACT>
__global__ void __launch_bounds__(256,2)
k_gemm_tc(const float* __restrict__ A, const float* __restrict__ bias){
    extern __shared__ float sm[];
    const uint32_t sb = s2u(sm);
    int tid = threadIdx.x, lane = tid&31, wid = tid>>5;
    int n0 = blockIdx.x*128, m0 = blockIdx.y*128;
    const float* Ab = A    + (size_t)m0*Dv;
    const float* Bb = g_WT + (size_t)n0*Dv;
    int g = lane>>2, t = lane&3;
    int wm = (wid&3)*32, wn = (wid>>2)*64;

    float acc[2][8][4];
    #pragma unroll
    for(int mi=0;mi<2;mi++)
        #pragma unroll
        for(int nj=0;nj<8;nj++)
            #pragma unroll
            for(int q=0;q<4;q++) acc[mi][nj][q]=0.f;

    auto stage = [&](int c, int buf){
        #pragma unroll
        for(int i=0;i<4;i++){
            int fi = tid + i*256;
            int row = fi>>3, k4 = (fi&7)<<2;
            const float* ga = Ab + (size_t)row*Dv + c*KC + k4;
            const float* gb = Bb + (size_t)row*Dv + c*KC + k4;
            uint32_t da = sb + (uint32_t)(buf*BUF_FLOATS + row*AS_STRIDE + k4)*4u;
            uint32_t db = da + ABUF_FLOATS*4u;
            asm volatile("cp.async.ca.shared.global [%0], [%1], 16;"::"r"(da),"l"(ga):"memory");
            asm volatile("cp.async.ca.shared.global [%0], [%1], 16;"::"r"(db),"l"(gb):"memory");
        }
        asm volatile("cp.async.commit_group;":::"memory");
    };

    stage(0,0);

    #pragma unroll 1
    for(int c=0;c<NCHUNK;c++){
        if(c+1<NCHUNK){
            stage(c+1,(c+1)&1);
            asm volatile("cp.async.wait_group 1;":::"memory");
        }else{
            asm volatile("cp.async.wait_group 0;":::"memory");
        }
        __syncthreads();
        const float* As = sm + (c&1)*BUF_FLOATS;
        const float* Bs = As + ABUF_FLOATS;
        #pragma unroll
        for(int ki=0;ki<4;ki++){
            uint32_t af[2][4];
            #pragma unroll
            for(int mi=0;mi<2;mi++){
                const float* p  = As + (wm+mi*16+g)*AS_STRIDE + ki*8 + t;
                const float* p8 = p + 8*AS_STRIDE;
                af[mi][0]=f2tf(p[0]);  af[mi][2]=f2tf(p[4]);
                af[mi][1]=f2tf(p8[0]); af[mi][3]=f2tf(p8[4]);
            }
            #pragma unroll
            for(int nj=0;nj<8;nj++){
                const float* q = Bs + (wn+nj*8+g)*AS_STRIDE + ki*8 + t;
                uint32_t b0=f2tf(q[0]), b1=f2tf(q[4]);
                mma_tf32(acc[0][nj], af[0], b0, b1);
                mma_tf32(acc[1][nj], af[1], b0, b1);
            }
        }
        __syncthreads();
    }

    // epilogue: bias + optional GELU, float2 stores
    #pragma unroll
    for(int mi=0;mi<2;mi++){
        int r0 = m0 + wm + mi*16 + g;
        #pragma unroll
        for(int nj=0;nj<8;nj++){
            int cc = n0 + wn + nj*8 + 2*t;
            float bb0=0.f, bb1=0.f;
            if(bias){ bb0 = bias[cc]; bb1 = bias[cc+1]; }
            float x0 = acc[mi][nj][0]+bb0, x1 = acc[mi][nj][1]+bb1;
            float x2 = acc[mi][nj][2]+bb0, x3 = acc[mi][nj][3]+bb1;
            if(ACT==1){ x0=gelu_exact(x0); x1=gelu_exact(x1); x2=gelu_exact(x2); x3=gelu_exact(x3); }
            float2 v0 = make_float2(x0,x1);
            float2 v1 = make_float2(x2,x3);
            *reinterpret_cast<float2*>(&g_H[(size_t)r0*Dv + cc])     = v0;
            *reinterpret_cast<float2*>(&g_H[(size_t)(r0+8)*Dv + cc]) = v1;
        }
    }
}

// ---------------- type head: LN + W2[512,6] + masked CE ----------------
__global__ void __launch_bounds__(256) k_type(const float* __restrict__ W2,
                                              const float* __restrict__ b2,
                                              const float* __restrict__ gam,
                                              const float* __restrict__ bet,
                                              const int* __restrict__ tgt){
    __shared__ float sh[8];
    int row = blockIdx.x, tid = threadIdx.x;
    const float* h = g_H + (size_t)row*Dv;
    float x0 = h[tid], x1 = h[tid+256];
    float mu  = blockReduceSum256(x0+x1, sh) * (1.f/Dv);
    float d0 = x0-mu, d1 = x1-mu;
    float var = blockReduceSum256(d0*d0 + d1*d1, sh) * (1.f/Dv);
    float rs = rsqrtf(var + 1e-5f);
    float y0 = d0*rs*gam[tid]     + bet[tid];
    float y1 = d1*rs*gam[tid+256] + bet[tid+256];
    float lg[6];
    #pragma unroll
    for(int c=0;c<6;c++){
        float p = y0*W2[tid*6+c] + y1*W2[(tid+256)*6+c];
        lg[c] = blockReduceSum256(p, sh);
    }
    if(tid==0){
        float mx = -1e30f;
        #pragma unroll
        for(int c=0;c<6;c++){ lg[c] += b2[c]; mx = fmaxf(mx, lg[c]); }
        float se = 0.f;
        #pragma unroll
        for(int c=0;c<6;c++) se += expf(lg[c]-mx);
        float lse = mx + logf(se);
        int t = tgt[row & (Nv-1)];
        g_part_t[row] = g_mask[row] * (lse - lg[t]);
    }
}

// ---------------- stats head: LN + W2[512,8] + masked MSE ----------------
__global__ void __launch_bounds__(256) k_stats(const float* __restrict__ W2,
                                               const float* __restrict__ b2,
                                               const float* __restrict__ gam,
                                               const float* __restrict__ bet,
                                               const float* __restrict__ st){
    __shared__ float sh[8];
    int row = blockIdx.x, tid = threadIdx.x;
    const float* h = g_H + (size_t)row*Dv;
    float x0 = h[tid], x1 = h[tid+256];
    float mu  = blockReduceSum256(x0+x1, sh) * (1.f/Dv);
    float d0 = x0-mu, d1 = x1-mu;
    float var = blockReduceSum256(d0*d0 + d1*d1, sh) * (1.f/Dv);
    float rs = rsqrtf(var + 1e-5f);
    float y0 = d0*rs*gam[tid]     + bet[tid];
    float y1 = d1*rs*gam[tid+256] + bet[tid+256];
    float pr[8];
    #pragma unroll
    for(int c=0;c<8;c++){
        float p = y0*W2[tid*8+c] + y1*W2[(tid+256)*8+c];
        pr[c] = blockReduceSum256(p, sh);
    }
    if(tid==0){
        float s = 0.f;
        #pragma unroll
        for(int c=0;c<8;c++){
            float d = pr[c] + b2[c] - st[(size_t)row*8 + c];
            s += d*d;
        }
        g_part_s[row] = g_mask[row] * s;
    }
}

// ---------------- correlation: per batch S = U @ E^T, tanh, diag=1, masked SE ----------------
__global__ void __launch_bounds__(256) k_corr(const float* __restrict__ E,
                                              const float* __restrict__ corr_t,
                                              const float* __restrict__ cb_ptr){
    __shared__ float Us[8][128];
    __shared__ float Es[8][128];
    __shared__ float sh[8];
    int b = blockIdx.x, tid = threadIdx.x;
    int tx = tid & 15, ty = tid >> 4;
    const float* U  = g_H + (size_t)b*Nv*Dv;
    const float* Eb = E   + (size_t)b*Nv*Dv;
    float acc[8][8];
    #pragma unroll
    for(int i=0;i<8;i++)
        #pragma unroll
        for(int j=0;j<8;j++) acc[i][j] = 0.f;
    int row = tid>>1, off = (tid&1)*4;
    for(int k0=0;k0<Dv;k0+=8){
        float4 a = *reinterpret_cast<const float4*>(&U [(size_t)row*Dv + k0 + off]);
        Us[off+0][row]=a.x; Us[off+1][row]=a.y; Us[off+2][row]=a.z; Us[off+3][row]=a.w;
        float4 e = *reinterpret_cast<const float4*>(&Eb[(size_t)row*Dv + k0 + off]);
        Es[off+0][row]=e.x; Es[off+1][row]=e.y; Es[off+2][row]=e.z; Es[off+3][row]=e.w;
        __syncthreads();
        #pragma unroll
        for(int k=0;k<8;k++){
            float ra[8], rb[8];
            #pragma unroll
            for(int i=0;i<8;i++) ra[i] = Us[k][ty*8+i];
            #pragma unroll
            for(int j=0;j<8;j++) rb[j] = Es[k][tx*8+j];
            #pragma unroll
            for(int i=0;i<8;i++)
                #pragma unroll
                for(int j=0;j<8;j++) acc[i][j] = fmaf(ra[i], rb[j], acc[i][j]);
        }
        __syncthreads();
    }
    float cb = *cb_ptr;
    float local = 0.f;
    #pragma unroll
    for(int i=0;i<8;i++){
        int gi = ty*8 + i;
        float mi = g_mask[b*Nv + gi];
        #pragma unroll
        for(int j=0;j<8;j++){
            int gj = tx*8 + j;
            float s = tanhf(acc[i][j] + cb);
            if(gi==gj) s = 1.f;
            float d = s - corr_t[(size_t)b*Nv*Nv + (size_t)gi*Nv + gj];
            float me = fmaxf(mi, g_mask[b*Nv + gj]);
            local += me*d*d;
        }
    }
    float tot = blockReduceSum256(local, sh);
    if(tid==0) g_part_c[b] = tot;
}

// ---------------- final deterministic combine ----------------
__global__ void k_final(float* __restrict__ out){
    __shared__ double sh[1024];
    int tid = threadIdx.x;
    double tsum=0, ssum=0, csum=0, nm=0, nme=0;
    for(int i=tid;i<BNv;i+=1024){ tsum += (double)g_part_t[i]; ssum += (double)g_part_s[i]; }
    for(int i=tid;i<Bv;i+=1024){
        csum += (double)g_part_c[i];
        double cnt = (double)g_cnt[i];
        nm += cnt;
        double u = (double)Nv - cnt;
        nme += (double)Nv*(double)Nv - u*u;
    }
    double vals[5] = {tsum, ssum, csum, nm, nme};
    for(int v=0;v<5;v++){
        sh[tid] = vals[v]; __syncthreads();
        for(int o=512;o>0;o>>=1){ if(tid<o) sh[tid]+=sh[tid+o]; __syncthreads(); }
        vals[v] = sh[0]; __syncthreads();
    }
    if(tid==0){
        double nm_  = vals[3] < 1.0 ? 1.0 : vals[3];
        double nme_ = vals[4] < 1.0 ? 1.0 : vals[4];
        double total = vals[0]/nm_ + vals[1]/(nm_*8.0) + 0.5*vals[2]/nme_;
        out[0] = (float)total;
    }
}

// ---------------- launch ----------------
extern "C" void kernel_launch(void* const* d_in, const int* in_sizes, int n_in,
                              void* d_out, int out_size){
    const float* e     = (const float*)d_in[0];
    const void*  mraw  = d_in[1];
    const int*   tgt   = (const int*)d_in[2];
    const float* stats = (const float*)d_in[3];
    const float* corr  = (const float*)d_in[4];
    const float* tW1  = (const float*)d_in[5];
    const float* tb1  = (const float*)d_in[6];
    const float* tg   = (const float*)d_in[7];
    const float* tbe  = (const float*)d_in[8];
    const float* tW2  = (const float*)d_in[9];
    const float* tb2  = (const float*)d_in[10];
    const float* sW1  = (const float*)d_in[11];
    const float* sb1  = (const float*)d_in[12];
    const float* sg   = (const float*)d_in[13];
    const float* sbe  = (const float*)d_in[14];
    const float* sW2  = (const float*)d_in[15];
    const float* sb2  = (const float*)d_in[16];
    const float* cW   = (const float*)d_in[17];
    const float* cb   = (const float*)d_in[18];

    static int s_init = 0;
    if(!s_init){
        cudaFuncSetAttribute(k_gemm_tc<1>, cudaFuncAttributeMaxDynamicSharedMemorySize, SMEM_SZ);
        cudaFuncSetAttribute(k_gemm_tc<0>, cudaFuncAttributeMaxDynamicSharedMemorySize, SMEM_SZ);
        s_init = 1;
    }

    k_detect<<<1,256>>>((const unsigned int*)mraw);
    k_expand_mask<<<BNv/256,256>>>(mraw);
    k_cnt<<<Bv,128>>>();

    dim3 gg(Dv/128, BNv/128);   // (4, 256)
    dim3 tg2(16,16), tb_(32,8);

    // type head
    k_transpose<<<tg2,tb_>>>(tW1);
    k_gemm_tc<1><<<gg,256,SMEM_SZ>>>(e, tb1);
    k_type<<<BNv,256>>>(tW2, tb2, tg, tbe, tgt);

    // stats head
    k_transpose<<<tg2,tb_>>>(sW1);
    k_gemm_tc<1><<<gg,256,SMEM_SZ>>>(e, sb1);
    k_stats<<<BNv,256>>>(sW2, sb2, sg, sbe, stats);

    // correlation: U = e @ c_W, then batched bilinear
    k_transpose<<<tg2,tb_>>>(cW);
    k_gemm_tc<0><<<gg,256,SMEM_SZ>>>(e, nullptr);
    k_corr<<<Bv,256>>>(e, corr, cb);

    k_final<<<1,1024>>>((float*)d_out);
}

// round 4
// speedup vs baseline: 2.7495x; 1.3880x over previous
#include <cuda_runtime.h>
#include <math.h>
#include <stdint.h>

#define Bv 256
#define Nv 128
#define Dv 512
#define BNv (Bv*Nv)

// ---------------- device scratch ----------------
__device__ float g_H[(size_t)BNv*Dv];    // 64 MB: H for heads / U (tf32-rounded) for corr
__device__ float g_E32[(size_t)BNv*Dv];  // 64 MB: tf32-rounded embeddings
__device__ float g_WT[3*Dv*Dv];          // 3 transposed+rounded weights
__device__ float g_mask[BNv];
__device__ float g_cnt[Bv];
__device__ float g_part_t[BNv];
__device__ float g_part_s[BNv];
__device__ float g_part_c[Bv];
__device__ int   g_mfmt;

// ---------------- helpers ----------------
__device__ __forceinline__ uint32_t s2u(const void* p){
    uint32_t a;
    asm("{ .reg .u64 t; cvta.to.shared.u64 t, %1; cvt.u32.u64 %0, t; }":"=r"(a):"l"(p));
    return a;
}
__device__ __forceinline__ float tf32r(float x){
    uint32_t r; asm("cvt.rna.tf32.f32 %0, %1;":"=r"(r):"f"(x));
    return __uint_as_float(r);
}
__device__ __forceinline__ void mma_tf32(float* d, const uint32_t* a, uint32_t b0, uint32_t b1){
    asm volatile(
      "mma.sync.aligned.m16n8k8.row.col.f32.tf32.tf32.f32 "
      "{%0,%1,%2,%3}, {%4,%5,%6,%7}, {%8,%9}, {%0,%1,%2,%3};"
      : "+f"(d[0]),"+f"(d[1]),"+f"(d[2]),"+f"(d[3])
      : "r"(a[0]),"r"(a[1]),"r"(a[2]),"r"(a[3]), "r"(b0),"r"(b1));
}
__device__ __forceinline__ float warpAllSum(float v){
    #pragma unroll
    for(int o=16;o>0;o>>=1) v += __shfl_xor_sync(0xffffffffu, v, o);
    return v;
}
__device__ __forceinline__ float gelu_exact(float x){
    return 0.5f*x*(1.0f + erff(x*0.70710678118654752f));
}

// ---------------- mask format detection / expansion ----------------
__global__ void k_detect(const unsigned int* __restrict__ raw){
    __shared__ int f[2];
    if(threadIdx.x==0){ f[0]=1; f[1]=1; }
    __syncthreads();
    for(int i=threadIdx.x;i<8192;i+=256){
        unsigned v = raw[i];
        if(v>1u) f[0]=0;
        if(v!=0u && v!=0x3F800000u) f[1]=0;
    }
    __syncthreads();
    if(threadIdx.x==0) g_mfmt = f[0] ? 0 : (f[1] ? 1 : 2);
}
__global__ void k_expand_mask(const void* __restrict__ raw){
    int i = blockIdx.x*blockDim.x + threadIdx.x;
    if(i>=BNv) return;
    int fmt = g_mfmt;
    float m;
    if(fmt==0)      m = (((const int*)raw)[i]   != 0)    ? 1.f : 0.f;
    else if(fmt==1) m = (((const float*)raw)[i] != 0.f)  ? 1.f : 0.f;
    else            m = (((const unsigned char*)raw)[i]!=0) ? 1.f : 0.f;
    g_mask[i] = m;
}
__global__ void k_cnt(){
    int b = blockIdx.x, tid = threadIdx.x;
    float v = g_mask[b*Nv + tid];
    #pragma unroll
    for(int o=16;o>0;o>>=1) v += __shfl_down_sync(0xffffffffu, v, o);
    __shared__ float sh[4];
    if((tid&31)==0) sh[tid>>5] = v;
    __syncthreads();
    if(tid==0) g_cnt[b] = sh[0]+sh[1]+sh[2]+sh[3];
}

// ---------------- pre-round e to tf32 ----------------
__global__ void k_round(const float* __restrict__ e){
    size_t i = (size_t)blockIdx.x*256 + threadIdx.x;
    float4 v = reinterpret_cast<const float4*>(e)[i];
    v.x=tf32r(v.x); v.y=tf32r(v.y); v.z=tf32r(v.z); v.w=tf32r(v.w);
    reinterpret_cast<float4*>(g_E32)[i] = v;
}

// ---------------- weight transpose + tf32 round: g_WT[z][n][k] = W[k][n] ----------------
__global__ void k_transpose3(const float* __restrict__ W0, const float* __restrict__ W1,
                             const float* __restrict__ W2){
    __shared__ float t[32][33];
    const float* W = (blockIdx.z==0) ? W0 : (blockIdx.z==1 ? W1 : W2);
    float* dst = g_WT + (size_t)blockIdx.z*Dv*Dv;
    int bx = blockIdx.x*32, by = blockIdx.y*32;
    int x = threadIdx.x, y = threadIdx.y;   // (32,8)
    #pragma unroll
    for(int i=0;i<32;i+=8) t[y+i][x] = W[(size_t)(by+y+i)*Dv + bx+x];
    __syncthreads();
    #pragma unroll
    for(int i=0;i<32;i+=8) dst[(size_t)(bx+y+i)*Dv + by+x] = tf32r(t[x][y+i]);
}

// ---------------- tf32 mma GEMM: g_H = act(E @ W + bias) ----------------
// A = g_E32 [BN,512] row-major (pre-rounded); B = g_WT slot [n][k] (pre-rounded).
#define KC 32
#define NCHUNK 16
#define AS_STRIDE 36
#define ABUF_FLOATS (128*AS_STRIDE)
#define BUF_FLOATS  (2*ABUF_FLOATS)
#define SMEM_SZ     (BUF_FLOATS*2*4)   // 73728 bytes

// ACT: 1 = +bias & exact GELU; 2 = no bias, tf32-round output (U for corr)
template<int ACT>
__global__ void __launch_bounds__(256,2)
k_gemm_tc(const float* __restrict__ bias, int wslot){
    extern __shared__ float sm[];
    const uint32_t sb = s2u(sm);
    int tid = threadIdx.x, lane = tid&31, wid = tid>>5;
    int n0 = blockIdx.x*128, m0 = blockIdx.y*128;
    const float* Ab = g_E32 + (size_t)m0*Dv;
    const float* Bb = g_WT + (size_t)wslot*Dv*Dv + (size_t)n0*Dv;
    int g = lane>>2, t = lane&3;
    int wm = (wid&3)*32, wn = (wid>>2)*64;

    float acc[2][8][4];
    #pragma unroll
    for(int mi=0;mi<2;mi++)
        #pragma unroll
        for(int nj=0;nj<8;nj++)
            #pragma unroll
            for(int q=0;q<4;q++) acc[mi][nj][q]=0.f;

    auto stage = [&](int c, int buf){
        #pragma unroll
        for(int i=0;i<4;i++){
            int fi = tid + i*256;
            int row = fi>>3, k4 = (fi&7)<<2;
            const float* ga = Ab + (size_t)row*Dv + c*KC + k4;
            const float* gb = Bb + (size_t)row*Dv + c*KC + k4;
            uint32_t da = sb + (uint32_t)(buf*BUF_FLOATS + row*AS_STRIDE + k4)*4u;
            uint32_t db = da + ABUF_FLOATS*4u;
            asm volatile("cp.async.ca.shared.global [%0], [%1], 16;"::"r"(da),"l"(ga):"memory");
            asm volatile("cp.async.ca.shared.global [%0], [%1], 16;"::"r"(db),"l"(gb):"memory");
        }
        asm volatile("cp.async.commit_group;":::"memory");
    };

    stage(0,0);

    #pragma unroll 1
    for(int c=0;c<NCHUNK;c++){
        if(c+1<NCHUNK){
            stage(c+1,(c+1)&1);
            asm volatile("cp.async.wait_group 1;":::"memory");
        }else{
            asm volatile("cp.async.wait_group 0;":::"memory");
        }
        __syncthreads();
        const float* As = sm + (c&1)*BUF_FLOATS;
        const float* Bs = As + ABUF_FLOATS;
        #pragma unroll
        for(int ki=0;ki<4;ki++){
            uint32_t af[2][4];
            #pragma unroll
            for(int mi=0;mi<2;mi++){
                const uint32_t* p  = (const uint32_t*)(As + (wm+mi*16+g)*AS_STRIDE + ki*8 + t);
                const uint32_t* p8 = p + 8*AS_STRIDE;
                af[mi][0]=p[0];  af[mi][2]=p[4];
                af[mi][1]=p8[0]; af[mi][3]=p8[4];
            }
            #pragma unroll
            for(int nj=0;nj<8;nj++){
                const uint32_t* q = (const uint32_t*)(Bs + (wn+nj*8+g)*AS_STRIDE + ki*8 + t);
                uint32_t b0=q[0], b1=q[4];
                mma_tf32(acc[0][nj], af[0], b0, b1);
                mma_tf32(acc[1][nj], af[1], b0, b1);
            }
        }
        __syncthreads();
    }

    #pragma unroll
    for(int mi=0;mi<2;mi++){
        int r0 = m0 + wm + mi*16 + g;
        #pragma unroll
        for(int nj=0;nj<8;nj++){
            int cc = n0 + wn + nj*8 + 2*t;
            float x0=acc[mi][nj][0], x1=acc[mi][nj][1], x2=acc[mi][nj][2], x3=acc[mi][nj][3];
            if(ACT==1){
                float bb0 = bias[cc], bb1 = bias[cc+1];
                x0=gelu_exact(x0+bb0); x1=gelu_exact(x1+bb1);
                x2=gelu_exact(x2+bb0); x3=gelu_exact(x3+bb1);
            }else{
                x0=tf32r(x0); x1=tf32r(x1); x2=tf32r(x2); x3=tf32r(x3);
            }
            *reinterpret_cast<float2*>(&g_H[(size_t)r0*Dv + cc])     = make_float2(x0,x1);
            *reinterpret_cast<float2*>(&g_H[(size_t)(r0+8)*Dv + cc]) = make_float2(x2,x3);
        }
    }
}

// ---------------- warp-per-row heads: LN + W2 + loss ----------------
__global__ void __launch_bounds__(256) k_type(const float* __restrict__ W2,
                                              const float* __restrict__ b2,
                                              const float* __restrict__ gam,
                                              const float* __restrict__ bet,
                                              const int* __restrict__ tgt){
    int wid = threadIdx.x>>5, lane = threadIdx.x&31;
    int row = blockIdx.x*8 + wid;
    const float4* h4 = reinterpret_cast<const float4*>(g_H + (size_t)row*Dv);
    float4 x[4];
    #pragma unroll
    for(int i=0;i<4;i++) x[i] = h4[lane + 32*i];
    float s = 0.f;
    #pragma unroll
    for(int i=0;i<4;i++) s += x[i].x+x[i].y+x[i].z+x[i].w;
    float mu = warpAllSum(s) * (1.f/Dv);
    float vv = 0.f;
    #pragma unroll
    for(int i=0;i<4;i++){
        float a=x[i].x-mu,b=x[i].y-mu,c=x[i].z-mu,d=x[i].w-mu;
        vv += a*a+b*b+c*c+d*d;
    }
    float rs = rsqrtf(warpAllSum(vv)*(1.f/Dv) + 1e-5f);
    float p[6] = {0,0,0,0,0,0};
    #pragma unroll
    for(int i=0;i<4;i++){
        int r0 = lane*4 + 128*i;
        float4 g4 = reinterpret_cast<const float4*>(gam)[lane+32*i];
        float4 b4 = reinterpret_cast<const float4*>(bet)[lane+32*i];
        float y[4];
        y[0]=(x[i].x-mu)*rs*g4.x+b4.x; y[1]=(x[i].y-mu)*rs*g4.y+b4.y;
        y[2]=(x[i].z-mu)*rs*g4.z+b4.z; y[3]=(x[i].w-mu)*rs*g4.w+b4.w;
        float wf[24];
        const float4* w4 = reinterpret_cast<const float4*>(W2 + (size_t)r0*6);
        #pragma unroll
        for(int j=0;j<6;j++) reinterpret_cast<float4*>(wf)[j] = w4[j];
        #pragma unroll
        for(int r=0;r<4;r++)
            #pragma unroll
            for(int c=0;c<6;c++) p[c] = fmaf(y[r], wf[r*6+c], p[c]);
    }
    #pragma unroll
    for(int c=0;c<6;c++) p[c] = warpAllSum(p[c]);
    if(lane==0){
        float mx = -1e30f;
        #pragma unroll
        for(int c=0;c<6;c++){ p[c] += b2[c]; mx = fmaxf(mx, p[c]); }
        float se = 0.f;
        #pragma unroll
        for(int c=0;c<6;c++) se += expf(p[c]-mx);
        float lse = mx + logf(se);
        int tt = tgt[row & (Nv-1)];
        g_part_t[row] = g_mask[row] * (lse - p[tt]);
    }
}

__global__ void __launch_bounds__(256) k_stats(const float* __restrict__ W2,
                                               const float* __restrict__ b2,
                                               const float* __restrict__ gam,
                                               const float* __restrict__ bet,
                                               const float* __restrict__ st){
    int wid = threadIdx.x>>5, lane = threadIdx.x&31;
    int row = blockIdx.x*8 + wid;
    const float4* h4 = reinterpret_cast<const float4*>(g_H + (size_t)row*Dv);
    float4 x[4];
    #pragma unroll
    for(int i=0;i<4;i++) x[i] = h4[lane + 32*i];
    float s = 0.f;
    #pragma unroll
    for(int i=0;i<4;i++) s += x[i].x+x[i].y+x[i].z+x[i].w;
    float mu = warpAllSum(s) * (1.f/Dv);
    float vv = 0.f;
    #pragma unroll
    for(int i=0;i<4;i++){
        float a=x[i].x-mu,b=x[i].y-mu,c=x[i].z-mu,d=x[i].w-mu;
        vv += a*a+b*b+c*c+d*d;
    }
    float rs = rsqrtf(warpAllSum(vv)*(1.f/Dv) + 1e-5f);
    float p[8] = {0,0,0,0,0,0,0,0};
    #pragma unroll
    for(int i=0;i<4;i++){
        int r0 = lane*4 + 128*i;
        float4 g4 = reinterpret_cast<const float4*>(gam)[lane+32*i];
        float4 b4 = reinterpret_cast<const float4*>(bet)[lane+32*i];
        float y[4];
        y[0]=(x[i].x-mu)*rs*g4.x+b4.x; y[1]=(x[i].y-mu)*rs*g4.y+b4.y;
        y[2]=(x[i].z-mu)*rs*g4.z+b4.z; y[3]=(x[i].w-mu)*rs*g4.w+b4.w;
        float wf[32];
        const float4* w4 = reinterpret_cast<const float4*>(W2 + (size_t)r0*8);
        #pragma unroll
        for(int j=0;j<8;j++) reinterpret_cast<float4*>(wf)[j] = w4[j];
        #pragma unroll
        for(int r=0;r<4;r++)
            #pragma unroll
            for(int c=0;c<8;c++) p[c] = fmaf(y[r], wf[r*8+c], p[c]);
    }
    #pragma unroll
    for(int c=0;c<8;c++) p[c] = warpAllSum(p[c]);
    if(lane==0){
        float ssum = 0.f;
        #pragma unroll
        for(int c=0;c<8;c++){
            float d = p[c] + b2[c] - st[(size_t)row*8 + c];
            ssum += d*d;
        }
        g_part_s[row] = g_mask[row] * ssum;
    }
}

// ---------------- corr via tf32 mma: per batch S = U @ E^T ----------------
__global__ void __launch_bounds__(256,2)
k_corr_tc(const float* __restrict__ corr_t, const float* __restrict__ cb_ptr){
    extern __shared__ float sm[];
    const uint32_t sb = s2u(sm);
    int tid = threadIdx.x, lane = tid&31, wid = tid>>5;
    int b = blockIdx.x;
    const float* Ab = g_H   + (size_t)b*Nv*Dv;   // U (tf32-rounded)
    const float* Bb = g_E32 + (size_t)b*Nv*Dv;   // E (tf32-rounded)
    int g = lane>>2, t = lane&3;
    int wm = (wid&3)*32, wn = (wid>>2)*64;

    float acc[2][8][4];
    #pragma unroll
    for(int mi=0;mi<2;mi++)
        #pragma unroll
        for(int nj=0;nj<8;nj++)
            #pragma unroll
            for(int q=0;q<4;q++) acc[mi][nj][q]=0.f;

    auto stage = [&](int c, int buf){
        #pragma unroll
        for(int i=0;i<4;i++){
            int fi = tid + i*256;
            int row = fi>>3, k4 = (fi&7)<<2;
            const float* ga = Ab + (size_t)row*Dv + c*KC + k4;
            const float* gb = Bb + (size_t)row*Dv + c*KC + k4;
            uint32_t da = sb + (uint32_t)(buf*BUF_FLOATS + row*AS_STRIDE + k4)*4u;
            uint32_t db = da + ABUF_FLOATS*4u;
            asm volatile("cp.async.ca.shared.global [%0], [%1], 16;"::"r"(da),"l"(ga):"memory");
            asm volatile("cp.async.ca.shared.global [%0], [%1], 16;"::"r"(db),"l"(gb):"memory");
        }
        asm volatile("cp.async.commit_group;":::"memory");
    };

    stage(0,0);

    #pragma unroll 1
    for(int c=0;c<NCHUNK;c++){
        if(c+1<NCHUNK){
            stage(c+1,(c+1)&1);
            asm volatile("cp.async.wait_group 1;":::"memory");
        }else{
            asm volatile("cp.async.wait_group 0;":::"memory");
        }
        __syncthreads();
        const float* As = sm + (c&1)*BUF_FLOATS;
        const float* Bs = As + ABUF_FLOATS;
        #pragma unroll
        for(int ki=0;ki<4;ki++){
            uint32_t af[2][4];
            #pragma unroll
            for(int mi=0;mi<2;mi++){
                const uint32_t* p  = (const uint32_t*)(As + (wm+mi*16+g)*AS_STRIDE + ki*8 + t);
                const uint32_t* p8 = p + 8*AS_STRIDE;
                af[mi][0]=p[0];  af[mi][2]=p[4];
                af[mi][1]=p8[0]; af[mi][3]=p8[4];
            }
            #pragma unroll
            for(int nj=0;nj<8;nj++){
                const uint32_t* q = (const uint32_t*)(Bs + (wn+nj*8+g)*AS_STRIDE + ki*8 + t);
                uint32_t b0=q[0], b1=q[4];
                mma_tf32(acc[0][nj], af[0], b0, b1);
                mma_tf32(acc[1][nj], af[1], b0, b1);
            }
        }
        __syncthreads();
    }

    float cb = *cb_ptr;
    const float* msk = g_mask + b*Nv;
    const float* ct  = corr_t + (size_t)b*Nv*Nv;
    float local = 0.f;
    #pragma unroll
    for(int mi=0;mi<2;mi++){
        int r0 = wm + mi*16 + g;
        float mr0 = msk[r0], mr8 = msk[r0+8];
        #pragma unroll
        for(int nj=0;nj<8;nj++){
            int cc = wn + nj*8 + 2*t;
            float mc0 = msk[cc], mc1 = msk[cc+1];
            float2 t0 = *reinterpret_cast<const float2*>(&ct[(size_t)r0*Nv + cc]);
            float2 t1 = *reinterpret_cast<const float2*>(&ct[(size_t)(r0+8)*Nv + cc]);
            float s0 = (r0==cc)     ? 1.f : tanhf(acc[mi][nj][0]+cb);
            float s1 = (r0==cc+1)   ? 1.f : tanhf(acc[mi][nj][1]+cb);
            float s2 = (r0+8==cc)   ? 1.f : tanhf(acc[mi][nj][2]+cb);
            float s3 = (r0+8==cc+1) ? 1.f : tanhf(acc[mi][nj][3]+cb);
            float d0=s0-t0.x, d1=s1-t0.y, d2=s2-t1.x, d3=s3-t1.y;
            local += fmaxf(mr0,mc0)*d0*d0 + fmaxf(mr0,mc1)*d1*d1
                   + fmaxf(mr8,mc0)*d2*d2 + fmaxf(mr8,mc1)*d3*d3;
        }
    }
    // reduce: warp, then cross-warp via (now dead) staging smem
    #pragma unroll
    for(int o=16;o>0;o>>=1) local += __shfl_down_sync(0xffffffffu, local, o);
    if(lane==0) sm[wid] = local;
    __syncthreads();
    if(tid==0){
        float tot = 0.f;
        #pragma unroll
        for(int w=0;w<8;w++) tot += sm[w];
        g_part_c[b] = tot;
    }
}

// ---------------- final deterministic combine ----------------
__global__ void k_final(float* __restrict__ out){
    __shared__ double sh[1024];
    int tid = threadIdx.x;
    double tsum=0, ssum=0, csum=0, nm=0, nme=0;
    for(int i=tid;i<BNv;i+=1024){ tsum += (double)g_part_t[i]; ssum += (double)g_part_s[i]; }
    for(int i=tid;i<Bv;i+=1024){
        csum += (double)g_part_c[i];
        double cnt = (double)g_cnt[i];
        nm += cnt;
        double u = (double)Nv - cnt;
        nme += (double)Nv*(double)Nv - u*u;
    }
    double vals[5] = {tsum, ssum, csum, nm, nme};
    for(int v=0;v<5;v++){
        sh[tid] = vals[v]; __syncthreads();
        for(int o=512;o>0;o>>=1){ if(tid<o) sh[tid]+=sh[tid+o]; __syncthreads(); }
        vals[v] = sh[0]; __syncthreads();
    }
    if(tid==0){
        double nm_  = vals[3] < 1.0 ? 1.0 : vals[3];
        double nme_ = vals[4] < 1.0 ? 1.0 : vals[4];
        double total = vals[0]/nm_ + vals[1]/(nm_*8.0) + 0.5*vals[2]/nme_;
        out[0] = (float)total;
    }
}

// ---------------- launch ----------------
extern "C" void kernel_launch(void* const* d_in, const int* in_sizes, int n_in,
                              void* d_out, int out_size){
    const float* e     = (const float*)d_in[0];
    const void*  mraw  = d_in[1];
    const int*   tgt   = (const int*)d_in[2];
    const float* stats = (const float*)d_in[3];
    const float* corr  = (const float*)d_in[4];
    const float* tW1  = (const float*)d_in[5];
    const float* tb1  = (const float*)d_in[6];
    const float* tg   = (const float*)d_in[7];
    const float* tbe  = (const float*)d_in[8];
    const float* tW2  = (const float*)d_in[9];
    const float* tb2  = (const float*)d_in[10];
    const float* sW1  = (const float*)d_in[11];
    const float* sb1  = (const float*)d_in[12];
    const float* sg   = (const float*)d_in[13];
    const float* sbe  = (const float*)d_in[14];
    const float* sW2  = (const float*)d_in[15];
    const float* sb2  = (const float*)d_in[16];
    const float* cW   = (const float*)d_in[17];
    const float* cb   = (const float*)d_in[18];

    static int s_init = 0;
    if(!s_init){
        cudaFuncSetAttribute(k_gemm_tc<1>, cudaFuncAttributeMaxDynamicSharedMemorySize, SMEM_SZ);
        cudaFuncSetAttribute(k_gemm_tc<2>, cudaFuncAttributeMaxDynamicSharedMemorySize, SMEM_SZ);
        cudaFuncSetAttribute(k_corr_tc,    cudaFuncAttributeMaxDynamicSharedMemorySize, SMEM_SZ);
        s_init = 1;
    }

    k_detect<<<1,256>>>((const unsigned int*)mraw);
    k_expand_mask<<<BNv/256,256>>>(mraw);
    k_cnt<<<Bv,128>>>();
    k_round<<<(BNv*(Dv/4))/256,256>>>(e);

    dim3 tg3(16,16,3), tb_(32,8);
    k_transpose3<<<tg3,tb_>>>(tW1, sW1, cW);

    dim3 gg(Dv/128, BNv/128);   // (4, 256)

    // type head
    k_gemm_tc<1><<<gg,256,SMEM_SZ>>>(tb1, 0);
    k_type<<<BNv/8,256>>>(tW2, tb2, tg, tbe, tgt);

    // stats head
    k_gemm_tc<1><<<gg,256,SMEM_SZ>>>(sb1, 1);
    k_stats<<<BNv/8,256>>>(sW2, sb2, sg, sbe, stats);

    // correlation: U = e @ c_W (rounded), then batched bilinear
    k_gemm_tc<2><<<gg,256,SMEM_SZ>>>(nullptr, 2);
    k_corr_tc<<<Bv,256,SMEM_SZ>>>(corr, cb);

    k_final<<<1,1024>>>((float*)d_out);
}

// round 5
// speedup vs baseline: 2.8857x; 1.0496x over previous
#include <cuda_runtime.h>
#include <math.h>
#include <stdint.h>

#define Bv 256
#define Nv 128
#define Dv 512
#define BNv (Bv*Nv)

// ---------------- device scratch ----------------
__device__ float g_H[(size_t)BNv*Dv];    // 64 MB: H for heads / U for corr
__device__ float g_WT[3*Dv*Dv];          // 3 transposed+rounded weights
__device__ float g_mask[BNv];
__device__ float g_cnt[Bv];
__device__ float g_part_t[BNv];
__device__ float g_part_s[BNv];
__device__ float g_part_c[Bv];
__device__ int   g_mfmt;

// ---------------- helpers ----------------
__device__ __forceinline__ uint32_t s2u(const void* p){
    uint32_t a;
    asm("{ .reg .u64 t; cvta.to.shared.u64 t, %1; cvt.u32.u64 %0, t; }":"=r"(a):"l"(p));
    return a;
}
__device__ __forceinline__ float tf32r(float x){
    uint32_t r; asm("cvt.rna.tf32.f32 %0, %1;":"=r"(r):"f"(x));
    return __uint_as_float(r);
}
__device__ __forceinline__ float htanh(float x){
    float t; asm("tanh.approx.f32 %0, %1;":"=f"(t):"f"(x));
    return t;
}
__device__ __forceinline__ float gelu_fast(float x){
    float x2 = x*x;
    float inner = x*fmaf(0.044715f*0.7978845608f, x2, 0.7978845608f);
    return 0.5f*x*(1.f + htanh(inner));
}
__device__ __forceinline__ void mma_tf32(float* d, const uint32_t* a, uint32_t b0, uint32_t b1){
    asm volatile(
      "mma.sync.aligned.m16n8k8.row.col.f32.tf32.tf32.f32 "
      "{%0,%1,%2,%3}, {%4,%5,%6,%7}, {%8,%9}, {%0,%1,%2,%3};"
      : "+f"(d[0]),"+f"(d[1]),"+f"(d[2]),"+f"(d[3])
      : "r"(a[0]),"r"(a[1]),"r"(a[2]),"r"(a[3]), "r"(b0),"r"(b1));
}
__device__ __forceinline__ float warpAllSum(float v){
    #pragma unroll
    for(int o=16;o>0;o>>=1) v += __shfl_xor_sync(0xffffffffu, v, o);
    return v;
}

// ---------------- mask format detection / expansion ----------------
__global__ void k_detect(const unsigned int* __restrict__ raw){
    __shared__ int f[2];
    if(threadIdx.x==0){ f[0]=1; f[1]=1; }
    __syncthreads();
    for(int i=threadIdx.x;i<8192;i+=256){
        unsigned v = raw[i];
        if(v>1u) f[0]=0;
        if(v!=0u && v!=0x3F800000u) f[1]=0;
    }
    __syncthreads();
    if(threadIdx.x==0) g_mfmt = f[0] ? 0 : (f[1] ? 1 : 2);
}
__global__ void k_expand_mask(const void* __restrict__ raw){
    int i = blockIdx.x*blockDim.x + threadIdx.x;
    if(i>=BNv) return;
    int fmt = g_mfmt;
    float m;
    if(fmt==0)      m = (((const int*)raw)[i]   != 0)    ? 1.f : 0.f;
    else if(fmt==1) m = (((const float*)raw)[i] != 0.f)  ? 1.f : 0.f;
    else            m = (((const unsigned char*)raw)[i]!=0) ? 1.f : 0.f;
    g_mask[i] = m;
}
__global__ void k_cnt(){
    int b = blockIdx.x, tid = threadIdx.x;
    float v = g_mask[b*Nv + tid];
    #pragma unroll
    for(int o=16;o>0;o>>=1) v += __shfl_down_sync(0xffffffffu, v, o);
    __shared__ float sh[4];
    if((tid&31)==0) sh[tid>>5] = v;
    __syncthreads();
    if(tid==0) g_cnt[b] = sh[0]+sh[1]+sh[2]+sh[3];
}

// ---------------- weight transpose + tf32 round: g_WT[z][n][k] = W[k][n] ----------------
__global__ void k_transpose3(const float* __restrict__ W0, const float* __restrict__ W1,
                             const float* __restrict__ W2){
    __shared__ float t[32][33];
    const float* W = (blockIdx.z==0) ? W0 : (blockIdx.z==1 ? W1 : W2);
    float* dst = g_WT + (size_t)blockIdx.z*Dv*Dv;
    int bx = blockIdx.x*32, by = blockIdx.y*32;
    int x = threadIdx.x, y = threadIdx.y;   // (32,8)
    #pragma unroll
    for(int i=0;i<32;i+=8) t[y+i][x] = W[(size_t)(by+y+i)*Dv + bx+x];
    __syncthreads();
    #pragma unroll
    for(int i=0;i<32;i+=8) dst[(size_t)(bx+y+i)*Dv + by+x] = tf32r(t[x][y+i]);
}

// ---------------- tf32 mma GEMM: g_H = act(E @ W + bias) ----------------
// A = e [BN,512] row-major (raw fp32, HW-truncated to tf32); B = g_WT slot [n][k].
#define KC 32
#define NCHUNK 16
#define AS_STRIDE 36
#define ABUF_FLOATS (128*AS_STRIDE)
#define BUF_FLOATS  (2*ABUF_FLOATS)
#define SMEM_SZ     (BUF_FLOATS*2*4)   // 73728 bytes

// ACT: 1 = +bias & GELU; 2 = raw accumulators (U for corr)
template<int ACT>
__global__ void __launch_bounds__(256,2)
k_gemm_tc(const float* __restrict__ A, const float* __restrict__ bias, int wslot){
    extern __shared__ float sm[];
    const uint32_t sb = s2u(sm);
    int tid = threadIdx.x, lane = tid&31, wid = tid>>5;
    int n0 = blockIdx.x*128, m0 = blockIdx.y*128;
    const float* Ab = A + (size_t)m0*Dv;
    const float* Bb = g_WT + (size_t)wslot*Dv*Dv + (size_t)n0*Dv;
    int g = lane>>2, t = lane&3;
    int wm = (wid&3)*32, wn = (wid>>2)*64;

    float acc[2][8][4];
    #pragma unroll
    for(int mi=0;mi<2;mi++)
        #pragma unroll
        for(int nj=0;nj<8;nj++)
            #pragma unroll
            for(int q=0;q<4;q++) acc[mi][nj][q]=0.f;

    auto stage = [&](int c, int buf){
        #pragma unroll
        for(int i=0;i<4;i++){
            int fi = tid + i*256;
            int row = fi>>3, k4 = (fi&7)<<2;
            const float* ga = Ab + (size_t)row*Dv + c*KC + k4;
            const float* gb = Bb + (size_t)row*Dv + c*KC + k4;
            uint32_t da = sb + (uint32_t)(buf*BUF_FLOATS + row*AS_STRIDE + k4)*4u;
            uint32_t db = da + ABUF_FLOATS*4u;
            asm volatile("cp.async.ca.shared.global [%0], [%1], 16;"::"r"(da),"l"(ga):"memory");
            asm volatile("cp.async.ca.shared.global [%0], [%1], 16;"::"r"(db),"l"(gb):"memory");
        }
        asm volatile("cp.async.commit_group;":::"memory");
    };

    stage(0,0);

    #pragma unroll 1
    for(int c=0;c<NCHUNK;c++){
        if(c+1<NCHUNK){
            stage(c+1,(c+1)&1);
            asm volatile("cp.async.wait_group 1;":::"memory");
        }else{
            asm volatile("cp.async.wait_group 0;":::"memory");
        }
        __syncthreads();
        const float* As = sm + (c&1)*BUF_FLOATS;
        const float* Bs = As + ABUF_FLOATS;
        #pragma unroll
        for(int ki=0;ki<4;ki++){
            uint32_t af[2][4];
            #pragma unroll
            for(int mi=0;mi<2;mi++){
                const uint32_t* p  = (const uint32_t*)(As + (wm+mi*16+g)*AS_STRIDE + ki*8 + t);
                const uint32_t* p8 = p + 8*AS_STRIDE;
                af[mi][0]=p[0];  af[mi][2]=p[4];
                af[mi][1]=p8[0]; af[mi][3]=p8[4];
            }
            #pragma unroll
            for(int nj=0;nj<8;nj++){
                const uint32_t* q = (const uint32_t*)(Bs + (wn+nj*8+g)*AS_STRIDE + ki*8 + t);
                uint32_t b0=q[0], b1=q[4];
                mma_tf32(acc[0][nj], af[0], b0, b1);
                mma_tf32(acc[1][nj], af[1], b0, b1);
            }
        }
        __syncthreads();
    }

    #pragma unroll
    for(int mi=0;mi<2;mi++){
        int r0 = m0 + wm + mi*16 + g;
        #pragma unroll
        for(int nj=0;nj<8;nj++){
            int cc = n0 + wn + nj*8 + 2*t;
            float x0=acc[mi][nj][0], x1=acc[mi][nj][1], x2=acc[mi][nj][2], x3=acc[mi][nj][3];
            if(ACT==1){
                float bb0 = bias[cc], bb1 = bias[cc+1];
                x0=gelu_fast(x0+bb0); x1=gelu_fast(x1+bb1);
                x2=gelu_fast(x2+bb0); x3=gelu_fast(x3+bb1);
            }
            *reinterpret_cast<float2*>(&g_H[(size_t)r0*Dv + cc])     = make_float2(x0,x1);
            *reinterpret_cast<float2*>(&g_H[(size_t)(r0+8)*Dv + cc]) = make_float2(x2,x3);
        }
    }
}

// ---------------- warp-per-row heads: LN + W2 + loss ----------------
__global__ void __launch_bounds__(256) k_type(const float* __restrict__ W2,
                                              const float* __restrict__ b2,
                                              const float* __restrict__ gam,
                                              const float* __restrict__ bet,
                                              const int* __restrict__ tgt){
    int wid = threadIdx.x>>5, lane = threadIdx.x&31;
    int row = blockIdx.x*8 + wid;
    const float4* h4 = reinterpret_cast<const float4*>(g_H + (size_t)row*Dv);
    float4 x[4];
    #pragma unroll
    for(int i=0;i<4;i++) x[i] = h4[lane + 32*i];
    float s = 0.f;
    #pragma unroll
    for(int i=0;i<4;i++) s += x[i].x+x[i].y+x[i].z+x[i].w;
    float mu = warpAllSum(s) * (1.f/Dv);
    float vv = 0.f;
    #pragma unroll
    for(int i=0;i<4;i++){
        float a=x[i].x-mu,b=x[i].y-mu,c=x[i].z-mu,d=x[i].w-mu;
        vv += a*a+b*b+c*c+d*d;
    }
    float rs = rsqrtf(warpAllSum(vv)*(1.f/Dv) + 1e-5f);
    float p[6] = {0,0,0,0,0,0};
    #pragma unroll
    for(int i=0;i<4;i++){
        int r0 = lane*4 + 128*i;
        float4 g4 = reinterpret_cast<const float4*>(gam)[lane+32*i];
        float4 b4 = reinterpret_cast<const float4*>(bet)[lane+32*i];
        float y[4];
        y[0]=(x[i].x-mu)*rs*g4.x+b4.x; y[1]=(x[i].y-mu)*rs*g4.y+b4.y;
        y[2]=(x[i].z-mu)*rs*g4.z+b4.z; y[3]=(x[i].w-mu)*rs*g4.w+b4.w;
        float wf[24];
        const float4* w4 = reinterpret_cast<const float4*>(W2 + (size_t)r0*6);
        #pragma unroll
        for(int j=0;j<6;j++) reinterpret_cast<float4*>(wf)[j] = w4[j];
        #pragma unroll
        for(int r=0;r<4;r++)
            #pragma unroll
            for(int c=0;c<6;c++) p[c] = fmaf(y[r], wf[r*6+c], p[c]);
    }
    #pragma unroll
    for(int c=0;c<6;c++) p[c] = warpAllSum(p[c]);
    if(lane==0){
        float mx = -1e30f;
        #pragma unroll
        for(int c=0;c<6;c++){ p[c] += b2[c]; mx = fmaxf(mx, p[c]); }
        float se = 0.f;
        #pragma unroll
        for(int c=0;c<6;c++) se += expf(p[c]-mx);
        float lse = mx + logf(se);
        int tt = tgt[row & (Nv-1)];
        g_part_t[row] = g_mask[row] * (lse - p[tt]);
    }
}

__global__ void __launch_bounds__(256) k_stats(const float* __restrict__ W2,
                                               const float* __restrict__ b2,
                                               const float* __restrict__ gam,
                                               const float* __restrict__ bet,
                                               const float* __restrict__ st){
    int wid = threadIdx.x>>5, lane = threadIdx.x&31;
    int row = blockIdx.x*8 + wid;
    const float4* h4 = reinterpret_cast<const float4*>(g_H + (size_t)row*Dv);
    float4 x[4];
    #pragma unroll
    for(int i=0;i<4;i++) x[i] = h4[lane + 32*i];
    float s = 0.f;
    #pragma unroll
    for(int i=0;i<4;i++) s += x[i].x+x[i].y+x[i].z+x[i].w;
    float mu = warpAllSum(s) * (1.f/Dv);
    float vv = 0.f;
    #pragma unroll
    for(int i=0;i<4;i++){
        float a=x[i].x-mu,b=x[i].y-mu,c=x[i].z-mu,d=x[i].w-mu;
        vv += a*a+b*b+c*c+d*d;
    }
    float rs = rsqrtf(warpAllSum(vv)*(1.f/Dv) + 1e-5f);
    float p[8] = {0,0,0,0,0,0,0,0};
    #pragma unroll
    for(int i=0;i<4;i++){
        int r0 = lane*4 + 128*i;
        float4 g4 = reinterpret_cast<const float4*>(gam)[lane+32*i];
        float4 b4 = reinterpret_cast<const float4*>(bet)[lane+32*i];
        float y[4];
        y[0]=(x[i].x-mu)*rs*g4.x+b4.x; y[1]=(x[i].y-mu)*rs*g4.y+b4.y;
        y[2]=(x[i].z-mu)*rs*g4.z+b4.z; y[3]=(x[i].w-mu)*rs*g4.w+b4.w;
        float wf[32];
        const float4* w4 = reinterpret_cast<const float4*>(W2 + (size_t)r0*8);
        #pragma unroll
        for(int j=0;j<8;j++) reinterpret_cast<float4*>(wf)[j] = w4[j];
        #pragma unroll
        for(int r=0;r<4;r++)
            #pragma unroll
            for(int c=0;c<8;c++) p[c] = fmaf(y[r], wf[r*8+c], p[c]);
    }
    #pragma unroll
    for(int c=0;c<8;c++) p[c] = warpAllSum(p[c]);
    if(lane==0){
        float ssum = 0.f;
        #pragma unroll
        for(int c=0;c<8;c++){
            float d = p[c] + b2[c] - st[(size_t)row*8 + c];
            ssum += d*d;
        }
        g_part_s[row] = g_mask[row] * ssum;
    }
}

// ---------------- corr via tf32 mma: per batch S = U @ E^T ----------------
__global__ void __launch_bounds__(256,2)
k_corr_tc(const float* __restrict__ E, const float* __restrict__ corr_t,
          const float* __restrict__ cb_ptr){
    extern __shared__ float sm[];
    const uint32_t sb = s2u(sm);
    int tid = threadIdx.x, lane = tid&31, wid = tid>>5;
    int b = blockIdx.x;
    const float* Ab = g_H + (size_t)b*Nv*Dv;   // U
    const float* Bb = E   + (size_t)b*Nv*Dv;   // raw e
    int g = lane>>2, t = lane&3;
    int wm = (wid&3)*32, wn = (wid>>2)*64;

    float acc[2][8][4];
    #pragma unroll
    for(int mi=0;mi<2;mi++)
        #pragma unroll
        for(int nj=0;nj<8;nj++)
            #pragma unroll
            for(int q=0;q<4;q++) acc[mi][nj][q]=0.f;

    auto stage = [&](int c, int buf){
        #pragma unroll
        for(int i=0;i<4;i++){
            int fi = tid + i*256;
            int row = fi>>3, k4 = (fi&7)<<2;
            const float* ga = Ab + (size_t)row*Dv + c*KC + k4;
            const float* gb = Bb + (size_t)row*Dv + c*KC + k4;
            uint32_t da = sb + (uint32_t)(buf*BUF_FLOATS + row*AS_STRIDE + k4)*4u;
            uint32_t db = da + ABUF_FLOATS*4u;
            asm volatile("cp.async.ca.shared.global [%0], [%1], 16;"::"r"(da),"l"(ga):"memory");
            asm volatile("cp.async.ca.shared.global [%0], [%1], 16;"::"r"(db),"l"(gb):"memory");
        }
        asm volatile("cp.async.commit_group;":::"memory");
    };

    stage(0,0);

    #pragma unroll 1
    for(int c=0;c<NCHUNK;c++){
        if(c+1<NCHUNK){
            stage(c+1,(c+1)&1);
            asm volatile("cp.async.wait_group 1;":::"memory");
        }else{
            asm volatile("cp.async.wait_group 0;":::"memory");
        }
        __syncthreads();
        const float* As = sm + (c&1)*BUF_FLOATS;
        const float* Bs = As + ABUF_FLOATS;
        #pragma unroll
        for(int ki=0;ki<4;ki++){
            uint32_t af[2][4];
            #pragma unroll
            for(int mi=0;mi<2;mi++){
                const uint32_t* p  = (const uint32_t*)(As + (wm+mi*16+g)*AS_STRIDE + ki*8 + t);
                const uint32_t* p8 = p + 8*AS_STRIDE;
                af[mi][0]=p[0];  af[mi][2]=p[4];
                af[mi][1]=p8[0]; af[mi][3]=p8[4];
            }
            #pragma unroll
            for(int nj=0;nj<8;nj++){
                const uint32_t* q = (const uint32_t*)(Bs + (wn+nj*8+g)*AS_STRIDE + ki*8 + t);
                uint32_t b0=q[0], b1=q[4];
                mma_tf32(acc[0][nj], af[0], b0, b1);
                mma_tf32(acc[1][nj], af[1], b0, b1);
            }
        }
        __syncthreads();
    }

    float cb = *cb_ptr;
    const float* msk = g_mask + b*Nv;
    const float* ct  = corr_t + (size_t)b*Nv*Nv;
    float local = 0.f;
    #pragma unroll
    for(int mi=0;mi<2;mi++){
        int r0 = wm + mi*16 + g;
        float mr0 = msk[r0], mr8 = msk[r0+8];
        #pragma unroll
        for(int nj=0;nj<8;nj++){
            int cc = wn + nj*8 + 2*t;
            float mc0 = msk[cc], mc1 = msk[cc+1];
            float2 t0 = *reinterpret_cast<const float2*>(&ct[(size_t)r0*Nv + cc]);
            float2 t1 = *reinterpret_cast<const float2*>(&ct[(size_t)(r0+8)*Nv + cc]);
            float s0 = (r0==cc)     ? 1.f : htanh(acc[mi][nj][0]+cb);
            float s1 = (r0==cc+1)   ? 1.f : htanh(acc[mi][nj][1]+cb);
            float s2 = (r0+8==cc)   ? 1.f : htanh(acc[mi][nj][2]+cb);
            float s3 = (r0+8==cc+1) ? 1.f : htanh(acc[mi][nj][3]+cb);
            float d0=s0-t0.x, d1=s1-t0.y, d2=s2-t1.x, d3=s3-t1.y;
            local += fmaxf(mr0,mc0)*d0*d0 + fmaxf(mr0,mc1)*d1*d1
                   + fmaxf(mr8,mc0)*d2*d2 + fmaxf(mr8,mc1)*d3*d3;
        }
    }
    #pragma unroll
    for(int o=16;o>0;o>>=1) local += __shfl_down_sync(0xffffffffu, local, o);
    if(lane==0) sm[wid] = local;
    __syncthreads();
    if(tid==0){
        float tot = 0.f;
        #pragma unroll
        for(int w=0;w<8;w++) tot += sm[w];
        g_part_c[b] = tot;
    }
}

// ---------------- final deterministic combine ----------------
__global__ void k_final(float* __restrict__ out){
    __shared__ double sh[1024];
    int tid = threadIdx.x;
    double tsum=0, ssum=0, csum=0, nm=0, nme=0;
    for(int i=tid;i<BNv;i+=1024){ tsum += (double)g_part_t[i]; ssum += (double)g_part_s[i]; }
    for(int i=tid;i<Bv;i+=1024){
        csum += (double)g_part_c[i];
        double cnt = (double)g_cnt[i];
        nm += cnt;
        double u = (double)Nv - cnt;
        nme += (double)Nv*(double)Nv - u*u;
    }
    double vals[5] = {tsum, ssum, csum, nm, nme};
    for(int v=0;v<5;v++){
        sh[tid] = vals[v]; __syncthreads();
        for(int o=512;o>0;o>>=1){ if(tid<o) sh[tid]+=sh[tid+o]; __syncthreads(); }
        vals[v] = sh[0]; __syncthreads();
    }
    if(tid==0){
        double nm_  = vals[3] < 1.0 ? 1.0 : vals[3];
        double nme_ = vals[4] < 1.0 ? 1.0 : vals[4];
        double total = vals[0]/nm_ + vals[1]/(nm_*8.0) + 0.5*vals[2]/nme_;
        out[0] = (float)total;
    }
}

// ---------------- launch ----------------
extern "C" void kernel_launch(void* const* d_in, const int* in_sizes, int n_in,
                              void* d_out, int out_size){
    const float* e     = (const float*)d_in[0];
    const void*  mraw  = d_in[1];
    const int*   tgt   = (const int*)d_in[2];
    const float* stats = (const float*)d_in[3];
    const float* corr  = (const float*)d_in[4];
    const float* tW1  = (const float*)d_in[5];
    const float* tb1  = (const float*)d_in[6];
    const float* tg   = (const float*)d_in[7];
    const float* tbe  = (const float*)d_in[8];
    const float* tW2  = (const float*)d_in[9];
    const float* tb2  = (const float*)d_in[10];
    const float* sW1  = (const float*)d_in[11];
    const float* sb1  = (const float*)d_in[12];
    const float* sg   = (const float*)d_in[13];
    const float* sbe  = (const float*)d_in[14];
    const float* sW2  = (const float*)d_in[15];
    const float* sb2  = (const float*)d_in[16];
    const float* cW   = (const float*)d_in[17];
    const float* cb   = (const float*)d_in[18];

    static int s_init = 0;
    if(!s_init){
        cudaFuncSetAttribute(k_gemm_tc<1>, cudaFuncAttributeMaxDynamicSharedMemorySize, SMEM_SZ);
        cudaFuncSetAttribute(k_gemm_tc<2>, cudaFuncAttributeMaxDynamicSharedMemorySize, SMEM_SZ);
        cudaFuncSetAttribute(k_corr_tc,    cudaFuncAttributeMaxDynamicSharedMemorySize, SMEM_SZ);
        s_init = 1;
    }

    k_detect<<<1,256>>>((const unsigned int*)mraw);
    k_expand_mask<<<BNv/256,256>>>(mraw);
    k_cnt<<<Bv,128>>>();

    dim3 tg3(16,16,3), tb_(32,8);
    k_transpose3<<<tg3,tb_>>>(tW1, sW1, cW);

    dim3 gg(Dv/128, BNv/128);   // (4, 256)

    // type head
    k_gemm_tc<1><<<gg,256,SMEM_SZ>>>(e, tb1, 0);
    k_type<<<BNv/8,256>>>(tW2, tb2, tg, tbe, tgt);

    // stats head
    k_gemm_tc<1><<<gg,256,SMEM_SZ>>>(e, sb1, 1);
    k_stats<<<BNv/8,256>>>(sW2, sb2, sg, sbe, stats);

    // correlation: U = e @ c_W, then batched bilinear
    k_gemm_tc<2><<<gg,256,SMEM_SZ>>>(e, nullptr, 2);
    k_corr_tc<<<Bv,256,SMEM_SZ>>>(e, corr, cb);

    k_final<<<1,1024>>>((float*)d_out);
}

// round 6
// speedup vs baseline: 3.8185x; 1.3232x over previous
#include <cuda_runtime.h>
#include <cuda_bf16.h>
#include <math.h>
#include <stdint.h>

#define Bv 256
#define Nv 128
#define Dv 512
#define BNv (Bv*Nv)

// ---------------- device scratch ----------------
__device__ float         g_H[(size_t)BNv*Dv];    // 64 MB: GELU(H) fp32 for heads
__device__ __nv_bfloat16 g_Ebf[(size_t)BNv*Dv];  // 32 MB: bf16 embeddings
__device__ __nv_bfloat16 g_Ubf[(size_t)BNv*Dv];  // 32 MB: bf16 U = e@cW
__device__ __nv_bfloat16 g_WTbf[3*Dv*Dv];        // 1.5 MB: transposed bf16 weights
__device__ float g_mask[BNv];
__device__ float g_cnt[Bv];
__device__ float g_part_t[BNv];
__device__ float g_part_s[BNv];
__device__ float g_part_c[Bv];
__device__ int   g_mfmt;

// ---------------- helpers ----------------
__device__ __forceinline__ uint32_t s2u(const void* p){
    uint32_t a;
    asm("{ .reg .u64 t; cvta.to.shared.u64 t, %1; cvt.u32.u64 %0, t; }":"=r"(a):"l"(p));
    return a;
}
__device__ __forceinline__ float htanh(float x){
    float t; asm("tanh.approx.f32 %0, %1;":"=f"(t):"f"(x));
    return t;
}
__device__ __forceinline__ float gelu_fast(float x){
    float x2 = x*x;
    float inner = x*fmaf(0.044715f*0.7978845608f, x2, 0.7978845608f);
    return 0.5f*x*(1.f + htanh(inner));
}
__device__ __forceinline__ void mma_bf16(float* d, const uint32_t* a, uint32_t b0, uint32_t b1){
    asm volatile(
      "mma.sync.aligned.m16n8k16.row.col.f32.bf16.bf16.f32 "
      "{%0,%1,%2,%3}, {%4,%5,%6,%7}, {%8,%9}, {%0,%1,%2,%3};"
      : "+f"(d[0]),"+f"(d[1]),"+f"(d[2]),"+f"(d[3])
      : "r"(a[0]),"r"(a[1]),"r"(a[2]),"r"(a[3]), "r"(b0),"r"(b1));
}
__device__ __forceinline__ float warpAllSum(float v){
    #pragma unroll
    for(int o=16;o>0;o>>=1) v += __shfl_xor_sync(0xffffffffu, v, o);
    return v;
}
__device__ __forceinline__ uint32_t packbf(float a, float b){
    __nv_bfloat162 p = __floats2bfloat162_rn(a,b);
    return *reinterpret_cast<uint32_t*>(&p);
}

// ---------------- mask format detection / expansion ----------------
__global__ void k_detect(const unsigned int* __restrict__ raw){
    __shared__ int f[2];
    if(threadIdx.x==0){ f[0]=1; f[1]=1; }
    __syncthreads();
    for(int i=threadIdx.x;i<8192;i+=256){
        unsigned v = raw[i];
        if(v>1u) f[0]=0;
        if(v!=0u && v!=0x3F800000u) f[1]=0;
    }
    __syncthreads();
    if(threadIdx.x==0) g_mfmt = f[0] ? 0 : (f[1] ? 1 : 2);
}
__global__ void k_expand_mask(const void* __restrict__ raw){
    int i = blockIdx.x*blockDim.x + threadIdx.x;
    if(i>=BNv) return;
    int fmt = g_mfmt;
    float m;
    if(fmt==0)      m = (((const int*)raw)[i]   != 0)    ? 1.f : 0.f;
    else if(fmt==1) m = (((const float*)raw)[i] != 0.f)  ? 1.f : 0.f;
    else            m = (((const unsigned char*)raw)[i]!=0) ? 1.f : 0.f;
    g_mask[i] = m;
}
__global__ void k_cnt(){
    int b = blockIdx.x, tid = threadIdx.x;
    float v = g_mask[b*Nv + tid];
    #pragma unroll
    for(int o=16;o>0;o>>=1) v += __shfl_down_sync(0xffffffffu, v, o);
    __shared__ float sh[4];
    if((tid&31)==0) sh[tid>>5] = v;
    __syncthreads();
    if(tid==0) g_cnt[b] = sh[0]+sh[1]+sh[2]+sh[3];
}

// ---------------- convert e -> bf16 ----------------
__global__ void k_cvt(const float* __restrict__ e){
    size_t i = (size_t)blockIdx.x*256 + threadIdx.x;   // one float4 each
    float4 v = reinterpret_cast<const float4*>(e)[i];
    uint2 o;
    o.x = packbf(v.x, v.y);
    o.y = packbf(v.z, v.w);
    reinterpret_cast<uint2*>(g_Ebf)[i] = o;
}

// ---------------- weight transpose -> bf16: g_WTbf[z][n][k] = W[k][n] ----------------
__global__ void k_transpose3(const float* __restrict__ W0, const float* __restrict__ W1,
                             const float* __restrict__ W2){
    __shared__ float t[32][33];
    const float* W = (blockIdx.z==0) ? W0 : (blockIdx.z==1 ? W1 : W2);
    __nv_bfloat16* dst = g_WTbf + (size_t)blockIdx.z*Dv*Dv;
    int bx = blockIdx.x*32, by = blockIdx.y*32;
    int x = threadIdx.x, y = threadIdx.y;   // (32,8)
    #pragma unroll
    for(int i=0;i<32;i+=8) t[y+i][x] = W[(size_t)(by+y+i)*Dv + bx+x];
    __syncthreads();
    #pragma unroll
    for(int i=0;i<32;i+=8) dst[(size_t)(bx+y+i)*Dv + by+x] = __float2bfloat16(t[x][y+i]);
}

// ---------------- bf16 mma GEMM core ----------------
// A [.,512] bf16 K-major rows; B [n][k] bf16. CTA tile 128x128, KC=64, 8 chunks.
// SMEM rows padded to 72 halves (144B) -> conflict-free frag words (4g+t).
#define NCHB   8
#define STH    72                       // halves per smem row
#define TILE_H (128*STH)                // 9216 halves per operand tile
#define BUFB   36864                    // bytes per stage (A+B)
#define SMEM_SZ (2*BUFB)                // 73728

// body macro-ish via template: OUT 1 = GELU->g_H fp32 ; 2 = raw->g_Ubf bf16 ; 3 = corr epilogue
template<int OUT>
__device__ __forceinline__ void gemm_body(
    const __nv_bfloat16* __restrict__ Ab, const __nv_bfloat16* __restrict__ Bb,
    float* sm, uint32_t sb, int m0, int n0,
    const float* __restrict__ bias,
    const float* __restrict__ corr_t, const float* __restrict__ cb_ptr, int b){

    int tid = threadIdx.x, lane = tid&31, wid = tid>>5;
    int g = lane>>2, t = lane&3;
    int wm = (wid&3)*32, wn = (wid>>2)*64;

    float acc[2][8][4];
    #pragma unroll
    for(int mi=0;mi<2;mi++)
        #pragma unroll
        for(int nj=0;nj<8;nj++)
            #pragma unroll
            for(int q=0;q<4;q++) acc[mi][nj][q]=0.f;

    auto stage = [&](int c, int buf){
        #pragma unroll
        for(int i=0;i<4;i++){
            int fi = tid + i*256;
            int row = fi>>3, q = fi&7;          // 8x16B granules per 128B row
            const __nv_bfloat16* ga = Ab + (size_t)row*Dv + c*64 + q*8;
            const __nv_bfloat16* gb = Bb + (size_t)row*Dv + c*64 + q*8;
            uint32_t da = sb + (uint32_t)(buf*BUFB + row*144 + q*16);
            uint32_t db = da + (uint32_t)(TILE_H*2);
            asm volatile("cp.async.ca.shared.global [%0], [%1], 16;"::"r"(da),"l"(ga):"memory");
            asm volatile("cp.async.ca.shared.global [%0], [%1], 16;"::"r"(db),"l"(gb):"memory");
        }
        asm volatile("cp.async.commit_group;":::"memory");
    };

    stage(0,0);

    #pragma unroll 1
    for(int c=0;c<NCHB;c++){
        if(c+1<NCHB){
            stage(c+1,(c+1)&1);
            asm volatile("cp.async.wait_group 1;":::"memory");
        }else{
            asm volatile("cp.async.wait_group 0;":::"memory");
        }
        __syncthreads();
        const uint32_t* Aw = reinterpret_cast<const uint32_t*>(sm) + (c&1)*(BUFB/4);
        const uint32_t* Bw = Aw + TILE_H/2;
        #pragma unroll
        for(int ki=0;ki<4;ki++){
            uint32_t af[2][4];
            #pragma unroll
            for(int mi=0;mi<2;mi++){
                const uint32_t* p0 = Aw + (wm+mi*16+g)*36   + ki*8 + t;
                const uint32_t* p1 = Aw + (wm+mi*16+g+8)*36 + ki*8 + t;
                af[mi][0]=p0[0]; af[mi][1]=p1[0]; af[mi][2]=p0[4]; af[mi][3]=p1[4];
            }
            #pragma unroll
            for(int nj=0;nj<8;nj++){
                const uint32_t* q = Bw + (wn+nj*8+g)*36 + ki*8 + t;
                uint32_t b0=q[0], b1=q[4];
                mma_bf16(acc[0][nj], af[0], b0, b1);
                mma_bf16(acc[1][nj], af[1], b0, b1);
            }
        }
        __syncthreads();
    }

    if(OUT==1){
        #pragma unroll
        for(int mi=0;mi<2;mi++){
            int r0 = m0 + wm + mi*16 + g;
            #pragma unroll
            for(int nj=0;nj<8;nj++){
                int cc = n0 + wn + nj*8 + 2*t;
                float bb0 = bias[cc], bb1 = bias[cc+1];
                float x0=gelu_fast(acc[mi][nj][0]+bb0), x1=gelu_fast(acc[mi][nj][1]+bb1);
                float x2=gelu_fast(acc[mi][nj][2]+bb0), x3=gelu_fast(acc[mi][nj][3]+bb1);
                *reinterpret_cast<float2*>(&g_H[(size_t)r0*Dv + cc])     = make_float2(x0,x1);
                *reinterpret_cast<float2*>(&g_H[(size_t)(r0+8)*Dv + cc]) = make_float2(x2,x3);
            }
        }
    }else if(OUT==2){
        #pragma unroll
        for(int mi=0;mi<2;mi++){
            int r0 = m0 + wm + mi*16 + g;
            #pragma unroll
            for(int nj=0;nj<8;nj++){
                int cc = n0 + wn + nj*8 + 2*t;
                *reinterpret_cast<uint32_t*>(&g_Ubf[(size_t)r0*Dv + cc])
                    = packbf(acc[mi][nj][0], acc[mi][nj][1]);
                *reinterpret_cast<uint32_t*>(&g_Ubf[(size_t)(r0+8)*Dv + cc])
                    = packbf(acc[mi][nj][2], acc[mi][nj][3]);
            }
        }
    }else{
        float cb = *cb_ptr;
        const float* msk = g_mask + b*Nv;
        const float* ct  = corr_t + (size_t)b*Nv*Nv;
        float local = 0.f;
        #pragma unroll
        for(int mi=0;mi<2;mi++){
            int r0 = wm + mi*16 + g;
            float mr0 = msk[r0], mr8 = msk[r0+8];
            #pragma unroll
            for(int nj=0;nj<8;nj++){
                int cc = wn + nj*8 + 2*t;
                float mc0 = msk[cc], mc1 = msk[cc+1];
                float2 t0 = *reinterpret_cast<const float2*>(&ct[(size_t)r0*Nv + cc]);
                float2 t1 = *reinterpret_cast<const float2*>(&ct[(size_t)(r0+8)*Nv + cc]);
                float s0 = (r0==cc)     ? 1.f : htanh(acc[0? (mi?0:0):(mi)][nj][0]+cb);
                // (note: index rewritten below for clarity)
                s0 = (r0==cc)     ? 1.f : htanh(acc[mi][nj][0]+cb);
                float s1 = (r0==cc+1)   ? 1.f : htanh(acc[mi][nj][1]+cb);
                float s2 = (r0+8==cc)   ? 1.f : htanh(acc[mi][nj][2]+cb);
                float s3 = (r0+8==cc+1) ? 1.f : htanh(acc[mi][nj][3]+cb);
                float d0=s0-t0.x, d1=s1-t0.y, d2=s2-t1.x, d3=s3-t1.y;
                local += fmaxf(mr0,mc0)*d0*d0 + fmaxf(mr0,mc1)*d1*d1
                       + fmaxf(mr8,mc0)*d2*d2 + fmaxf(mr8,mc1)*d3*d3;
            }
        }
        #pragma unroll
        for(int o=16;o>0;o>>=1) local += __shfl_down_sync(0xffffffffu, local, o);
        if(lane==0) sm[wid] = local;
        __syncthreads();
        if(tid==0){
            float tot = 0.f;
            #pragma unroll
            for(int w=0;w<8;w++) tot += sm[w];
            g_part_c[b] = tot;
        }
    }
}

// OUT 1/2: dense GEMM over g_Ebf x g_WTbf
template<int OUT>
__global__ void __launch_bounds__(256,2)
k_gemm_bf(const float* __restrict__ bias, int wslot){
    extern __shared__ float sm[];
    uint32_t sb = s2u(sm);
    int n0 = blockIdx.x*128, m0 = blockIdx.y*128;
    const __nv_bfloat16* Ab = g_Ebf + (size_t)m0*Dv;
    const __nv_bfloat16* Bb = g_WTbf + (size_t)wslot*Dv*Dv + (size_t)n0*Dv;
    gemm_body<OUT>(Ab, Bb, sm, sb, m0, n0, bias, nullptr, nullptr, 0);
}

// corr: per-batch U @ E^T with fused loss epilogue
__global__ void __launch_bounds__(256,2)
k_corr_bf(const float* __restrict__ corr_t, const float* __restrict__ cb_ptr){
    extern __shared__ float sm[];
    uint32_t sb = s2u(sm);
    int b = blockIdx.x;
    const __nv_bfloat16* Ab = g_Ubf + (size_t)b*Nv*Dv;
    const __nv_bfloat16* Bb = g_Ebf + (size_t)b*Nv*Dv;
    gemm_body<3>(Ab, Bb, sm, sb, 0, 0, nullptr, corr_t, cb_ptr, b);
}

// ---------------- warp-per-row heads: LN + W2 + loss ----------------
__global__ void __launch_bounds__(256) k_type(const float* __restrict__ W2,
                                              const float* __restrict__ b2,
                                              const float* __restrict__ gam,
                                              const float* __restrict__ bet,
                                              const int* __restrict__ tgt){
    int wid = threadIdx.x>>5, lane = threadIdx.x&31;
    int row = blockIdx.x*8 + wid;
    const float4* h4 = reinterpret_cast<const float4*>(g_H + (size_t)row*Dv);
    float4 x[4];
    #pragma unroll
    for(int i=0;i<4;i++) x[i] = h4[lane + 32*i];
    float s = 0.f;
    #pragma unroll
    for(int i=0;i<4;i++) s += x[i].x+x[i].y+x[i].z+x[i].w;
    float mu = warpAllSum(s) * (1.f/Dv);
    float vv = 0.f;
    #pragma unroll
    for(int i=0;i<4;i++){
        float a=x[i].x-mu,b=x[i].y-mu,c=x[i].z-mu,d=x[i].w-mu;
        vv += a*a+b*b+c*c+d*d;
    }
    float rs = rsqrtf(warpAllSum(vv)*(1.f/Dv) + 1e-5f);
    float p[6] = {0,0,0,0,0,0};
    #pragma unroll
    for(int i=0;i<4;i++){
        int r0 = lane*4 + 128*i;
        float4 g4 = reinterpret_cast<const float4*>(gam)[lane+32*i];
        float4 b4 = reinterpret_cast<const float4*>(bet)[lane+32*i];
        float y[4];
        y[0]=(x[i].x-mu)*rs*g4.x+b4.x; y[1]=(x[i].y-mu)*rs*g4.y+b4.y;
        y[2]=(x[i].z-mu)*rs*g4.z+b4.z; y[3]=(x[i].w-mu)*rs*g4.w+b4.w;
        float wf[24];
        const float4* w4 = reinterpret_cast<const float4*>(W2 + (size_t)r0*6);
        #pragma unroll
        for(int j=0;j<6;j++) reinterpret_cast<float4*>(wf)[j] = w4[j];
        #pragma unroll
        for(int r=0;r<4;r++)
            #pragma unroll
            for(int c=0;c<6;c++) p[c] = fmaf(y[r], wf[r*6+c], p[c]);
    }
    #pragma unroll
    for(int c=0;c<6;c++) p[c] = warpAllSum(p[c]);
    if(lane==0){
        float mx = -1e30f;
        #pragma unroll
        for(int c=0;c<6;c++){ p[c] += b2[c]; mx = fmaxf(mx, p[c]); }
        float se = 0.f;
        #pragma unroll
        for(int c=0;c<6;c++) se += expf(p[c]-mx);
        float lse = mx + logf(se);
        int tt = tgt[row & (Nv-1)];
        g_part_t[row] = g_mask[row] * (lse - p[tt]);
    }
}

__global__ void __launch_bounds__(256) k_stats(const float* __restrict__ W2,
                                               const float* __restrict__ b2,
                                               const float* __restrict__ gam,
                                               const float* __restrict__ bet,
                                               const float* __restrict__ st){
    int wid = threadIdx.x>>5, lane = threadIdx.x&31;
    int row = blockIdx.x*8 + wid;
    const float4* h4 = reinterpret_cast<const float4*>(g_H + (size_t)row*Dv);
    float4 x[4];
    #pragma unroll
    for(int i=0;i<4;i++) x[i] = h4[lane + 32*i];
    float s = 0.f;
    #pragma unroll
    for(int i=0;i<4;i++) s += x[i].x+x[i].y+x[i].z+x[i].w;
    float mu = warpAllSum(s) * (1.f/Dv);
    float vv = 0.f;
    #pragma unroll
    for(int i=0;i<4;i++){
        float a=x[i].x-mu,b=x[i].y-mu,c=x[i].z-mu,d=x[i].w-mu;
        vv += a*a+b*b+c*c+d*d;
    }
    float rs = rsqrtf(warpAllSum(vv)*(1.f/Dv) + 1e-5f);
    float p[8] = {0,0,0,0,0,0,0,0};
    #pragma unroll
    for(int i=0;i<4;i++){
        int r0 = lane*4 + 128*i;
        float4 g4 = reinterpret_cast<const float4*>(gam)[lane+32*i];
        float4 b4 = reinterpret_cast<const float4*>(bet)[lane+32*i];
        float y[4];
        y[0]=(x[i].x-mu)*rs*g4.x+b4.x; y[1]=(x[i].y-mu)*rs*g4.y+b4.y;
        y[2]=(x[i].z-mu)*rs*g4.z+b4.z; y[3]=(x[i].w-mu)*rs*g4.w+b4.w;
        float wf[32];
        const float4* w4 = reinterpret_cast<const float4*>(W2 + (size_t)r0*8);
        #pragma unroll
        for(int j=0;j<8;j++) reinterpret_cast<float4*>(wf)[j] = w4[j];
        #pragma unroll
        for(int r=0;r<4;r++)
            #pragma unroll
            for(int c=0;c<8;c++) p[c] = fmaf(y[r], wf[r*8+c], p[c]);
    }
    #pragma unroll
    for(int c=0;c<8;c++) p[c] = warpAllSum(p[c]);
    if(lane==0){
        float ssum = 0.f;
        #pragma unroll
        for(int c=0;c<8;c++){
            float d = p[c] + b2[c] - st[(size_t)row*8 + c];
            ssum += d*d;
        }
        g_part_s[row] = g_mask[row] * ssum;
    }
}

// ---------------- final deterministic combine ----------------
__global__ void k_final(float* __restrict__ out){
    __shared__ double sh[1024];
    int tid = threadIdx.x;
    double tsum=0, ssum=0, csum=0, nm=0, nme=0;
    for(int i=tid;i<BNv;i+=1024){ tsum += (double)g_part_t[i]; ssum += (double)g_part_s[i]; }
    for(int i=tid;i<Bv;i+=1024){
        csum += (double)g_part_c[i];
        double cnt = (double)g_cnt[i];
        nm += cnt;
        double u = (double)Nv - cnt;
        nme += (double)Nv*(double)Nv - u*u;
    }
    double vals[5] = {tsum, ssum, csum, nm, nme};
    for(int v=0;v<5;v++){
        sh[tid] = vals[v]; __syncthreads();
        for(int o=512;o>0;o>>=1){ if(tid<o) sh[tid]+=sh[tid+o]; __syncthreads(); }
        vals[v] = sh[0]; __syncthreads();
    }
    if(tid==0){
        double nm_  = vals[3] < 1.0 ? 1.0 : vals[3];
        double nme_ = vals[4] < 1.0 ? 1.0 : vals[4];
        double total = vals[0]/nm_ + vals[1]/(nm_*8.0) + 0.5*vals[2]/nme_;
        out[0] = (float)total;
    }
}

// ---------------- launch ----------------
extern "C" void kernel_launch(void* const* d_in, const int* in_sizes, int n_in,
                              void* d_out, int out_size){
    const float* e     = (const float*)d_in[0];
    const void*  mraw  = d_in[1];
    const int*   tgt   = (const int*)d_in[2];
    const float* stats = (const float*)d_in[3];
    const float* corr  = (const float*)d_in[4];
    const float* tW1  = (const float*)d_in[5];
    const float* tb1  = (const float*)d_in[6];
    const float* tg   = (const float*)d_in[7];
    const float* tbe  = (const float*)d_in[8];
    const float* tW2  = (const float*)d_in[9];
    const float* tb2  = (const float*)d_in[10];
    const float* sW1  = (const float*)d_in[11];
    const float* sb1  = (const float*)d_in[12];
    const float* sg   = (const float*)d_in[13];
    const float* sbe  = (const float*)d_in[14];
    const float* sW2  = (const float*)d_in[15];
    const float* sb2  = (const float*)d_in[16];
    const float* cW   = (const float*)d_in[17];
    const float* cb   = (const float*)d_in[18];

    static int s_init = 0;
    if(!s_init){
        cudaFuncSetAttribute(k_gemm_bf<1>, cudaFuncAttributeMaxDynamicSharedMemorySize, SMEM_SZ);
        cudaFuncSetAttribute(k_gemm_bf<2>, cudaFuncAttributeMaxDynamicSharedMemorySize, SMEM_SZ);
        cudaFuncSetAttribute(k_corr_bf,    cudaFuncAttributeMaxDynamicSharedMemorySize, SMEM_SZ);
        s_init = 1;
    }

    k_detect<<<1,256>>>((const unsigned int*)mraw);
    k_expand_mask<<<BNv/256,256>>>(mraw);
    k_cnt<<<Bv,128>>>();
    k_cvt<<<(BNv*(Dv/4))/256,256>>>(e);

    dim3 tg3(16,16,3), tb_(32,8);
    k_transpose3<<<tg3,tb_>>>(tW1, sW1, cW);

    dim3 gg(Dv/128, BNv/128);   // (4, 256)

    // type head
    k_gemm_bf<1><<<gg,256,SMEM_SZ>>>(tb1, 0);
    k_type<<<BNv/8,256>>>(tW2, tb2, tg, tbe, tgt);

    // stats head
    k_gemm_bf<1><<<gg,256,SMEM_SZ>>>(sb1, 1);
    k_stats<<<BNv/8,256>>>(sW2, sb2, sg, sbe, stats);

    // correlation: U = e @ c_W (bf16), then batched bilinear + fused loss
    k_gemm_bf<2><<<gg,256,SMEM_SZ>>>(nullptr, 2);
    k_corr_bf<<<Bv,256,SMEM_SZ>>>(corr, cb);

    k_final<<<1,1024>>>((float*)d_out);
}

// round 7
// speedup vs baseline: 3.9986x; 1.0472x over previous
#include <cuda_runtime.h>
#include <cuda_bf16.h>
#include <math.h>
#include <stdint.h>

#define Bv 256
#define Nv 128
#define Dv 512
#define BNv (Bv*Nv)

// ---------------- device scratch ----------------
__device__ float         g_H [(size_t)BNv*Dv];   // 64 MB: GELU(H) type head
__device__ float         g_H2[(size_t)BNv*Dv];   // 64 MB: GELU(H) stats head
__device__ __nv_bfloat16 g_Ebf[(size_t)BNv*Dv];  // 32 MB
__device__ __nv_bfloat16 g_Ubf[(size_t)BNv*Dv];  // 32 MB
__device__ __nv_bfloat16 g_WTbf[3*Dv*Dv];
__device__ float g_mask[BNv];
__device__ float g_cnt[Bv];
__device__ float g_part_t[BNv];
__device__ float g_part_s[BNv];
__device__ float g_part_c[Bv];
__device__ int   g_mfmt;

// ---------------- helpers ----------------
__device__ __forceinline__ uint32_t s2u(const void* p){
    uint32_t a;
    asm("{ .reg .u64 t; cvta.to.shared.u64 t, %1; cvt.u32.u64 %0, t; }":"=r"(a):"l"(p));
    return a;
}
__device__ __forceinline__ float htanh(float x){
    float t; asm("tanh.approx.f32 %0, %1;":"=f"(t):"f"(x));
    return t;
}
__device__ __forceinline__ float gelu_fast(float x){
    float x2 = x*x;
    float inner = x*fmaf(0.044715f*0.7978845608f, x2, 0.7978845608f);
    return 0.5f*x*(1.f + htanh(inner));
}
__device__ __forceinline__ void mma_bf16(float* d, const uint32_t* a, uint32_t b0, uint32_t b1){
    asm volatile(
      "mma.sync.aligned.m16n8k16.row.col.f32.bf16.bf16.f32 "
      "{%0,%1,%2,%3}, {%4,%5,%6,%7}, {%8,%9}, {%0,%1,%2,%3};"
      : "+f"(d[0]),"+f"(d[1]),"+f"(d[2]),"+f"(d[3])
      : "r"(a[0]),"r"(a[1]),"r"(a[2]),"r"(a[3]), "r"(b0),"r"(b1));
}
__device__ __forceinline__ void ldsm4(uint32_t addr, uint32_t* r){
    asm volatile("ldmatrix.sync.aligned.m8n8.x4.shared.b16 {%0,%1,%2,%3}, [%4];"
        : "=r"(r[0]),"=r"(r[1]),"=r"(r[2]),"=r"(r[3]) : "r"(addr));
}
__device__ __forceinline__ float warpAllSum(float v){
    #pragma unroll
    for(int o=16;o>0;o>>=1) v += __shfl_xor_sync(0xffffffffu, v, o);
    return v;
}
__device__ __forceinline__ uint32_t packbf(float a, float b){
    __nv_bfloat162 p = __floats2bfloat162_rn(a,b);
    return *reinterpret_cast<uint32_t*>(&p);
}

// ---------------- mask format detection / expansion ----------------
__global__ void k_detect(const unsigned int* __restrict__ raw){
    __shared__ int f[2];
    if(threadIdx.x==0){ f[0]=1; f[1]=1; }
    __syncthreads();
    for(int i=threadIdx.x;i<8192;i+=256){
        unsigned v = raw[i];
        if(v>1u) f[0]=0;
        if(v!=0u && v!=0x3F800000u) f[1]=0;
    }
    __syncthreads();
    if(threadIdx.x==0) g_mfmt = f[0] ? 0 : (f[1] ? 1 : 2);
}
__global__ void k_expand_mask(const void* __restrict__ raw){
    int i = blockIdx.x*blockDim.x + threadIdx.x;
    if(i>=BNv) return;
    int fmt = g_mfmt;
    float m;
    if(fmt==0)      m = (((const int*)raw)[i]   != 0)    ? 1.f : 0.f;
    else if(fmt==1) m = (((const float*)raw)[i] != 0.f)  ? 1.f : 0.f;
    else            m = (((const unsigned char*)raw)[i]!=0) ? 1.f : 0.f;
    g_mask[i] = m;
}
__global__ void k_cnt(){
    int b = blockIdx.x, tid = threadIdx.x;
    float v = g_mask[b*Nv + tid];
    #pragma unroll
    for(int o=16;o>0;o>>=1) v += __shfl_down_sync(0xffffffffu, v, o);
    __shared__ float sh[4];
    if((tid&31)==0) sh[tid>>5] = v;
    __syncthreads();
    if(tid==0) g_cnt[b] = sh[0]+sh[1]+sh[2]+sh[3];
}

// ---------------- convert e -> bf16 ----------------
__global__ void k_cvt(const float* __restrict__ e){
    size_t i = (size_t)blockIdx.x*256 + threadIdx.x;
    float4 v = reinterpret_cast<const float4*>(e)[i];
    uint2 o;
    o.x = packbf(v.x, v.y);
    o.y = packbf(v.z, v.w);
    reinterpret_cast<uint2*>(g_Ebf)[i] = o;
}

// ---------------- weight transpose -> bf16 ----------------
__global__ void k_transpose3(const float* __restrict__ W0, const float* __restrict__ W1,
                             const float* __restrict__ W2){
    __shared__ float t[32][33];
    const float* W = (blockIdx.z==0) ? W0 : (blockIdx.z==1 ? W1 : W2);
    __nv_bfloat16* dst = g_WTbf + (size_t)blockIdx.z*Dv*Dv;
    int bx = blockIdx.x*32, by = blockIdx.y*32;
    int x = threadIdx.x, y = threadIdx.y;
    #pragma unroll
    for(int i=0;i<32;i+=8) t[y+i][x] = W[(size_t)(by+y+i)*Dv + bx+x];
    __syncthreads();
    #pragma unroll
    for(int i=0;i<32;i+=8) dst[(size_t)(bx+y+i)*Dv + by+x] = __float2bfloat16(t[x][y+i]);
}

// ---------------- bf16 mma GEMM core (ldmatrix mainloop) ----------------
#define NCHB   8
#define STH    72                       // halves per smem row (144 B)
#define TILE_H (128*STH)
#define BUFB   36864
#define SMEM_SZ (2*BUFB)                // 73728

// OUT 1 = GELU->g_H ; 2 = GELU->g_H2 ; 3 = bf16 U -> g_Ubf ; 4 = corr epilogue
template<int OUT>
__device__ __forceinline__ void gemm_body(
    const __nv_bfloat16* __restrict__ Ab, const __nv_bfloat16* __restrict__ Bb,
    float* sm, uint32_t sb, int m0, int n0,
    const float* __restrict__ bias,
    const float* __restrict__ corr_t, const float* __restrict__ cb_ptr, int b){

    int tid = threadIdx.x, lane = tid&31, wid = tid>>5;
    int g = lane>>2, t = lane&3;
    int wm = (wid&3)*32, wn = (wid>>2)*64;

    // ldmatrix per-lane base offsets (bytes within a stage buffer)
    int lrow = lane&15, lhi = lane>>4;   // lhi: k half-offset (16B)
    uint32_t aoff[2], boff[4];
    #pragma unroll
    for(int mi=0;mi<2;mi++)
        aoff[mi] = (uint32_t)(((wm+mi*16+lrow)*36 + lhi*4)*4);
    #pragma unroll
    for(int p=0;p<4;p++)
        boff[p]  = (uint32_t)(TILE_H*2 + ((wn+p*16+lrow)*36 + lhi*4)*4);

    float acc[2][8][4];
    #pragma unroll
    for(int mi=0;mi<2;mi++)
        #pragma unroll
        for(int nj=0;nj<8;nj++)
            #pragma unroll
            for(int q=0;q<4;q++) acc[mi][nj][q]=0.f;

    auto stage = [&](int c, int buf){
        #pragma unroll
        for(int i=0;i<4;i++){
            int fi = tid + i*256;
            int row = fi>>3, q = fi&7;
            const __nv_bfloat16* ga = Ab + (size_t)row*Dv + c*64 + q*8;
            const __nv_bfloat16* gb = Bb + (size_t)row*Dv + c*64 + q*8;
            uint32_t da = sb + (uint32_t)(buf*BUFB + row*144 + q*16);
            uint32_t db = da + (uint32_t)(TILE_H*2);
            asm volatile("cp.async.ca.shared.global [%0], [%1], 16;"::"r"(da),"l"(ga):"memory");
            asm volatile("cp.async.ca.shared.global [%0], [%1], 16;"::"r"(db),"l"(gb):"memory");
        }
        asm volatile("cp.async.commit_group;":::"memory");
    };

    stage(0,0);

    #pragma unroll 1
    for(int c=0;c<NCHB;c++){
        if(c+1<NCHB){
            stage(c+1,(c+1)&1);
            asm volatile("cp.async.wait_group 1;":::"memory");
        }else{
            asm volatile("cp.async.wait_group 0;":::"memory");
        }
        __syncthreads();
        uint32_t base = sb + (uint32_t)((c&1)*BUFB);
        #pragma unroll
        for(int ki=0;ki<4;ki++){
            uint32_t af[2][4], bf[4][4];
            ldsm4(base + aoff[0] + ki*32, af[0]);
            ldsm4(base + aoff[1] + ki*32, af[1]);
            #pragma unroll
            for(int p=0;p<4;p++) ldsm4(base + boff[p] + ki*32, bf[p]);
            #pragma unroll
            for(int p=0;p<4;p++){
                mma_bf16(acc[0][2*p],   af[0], bf[p][0], bf[p][2]);
                mma_bf16(acc[1][2*p],   af[1], bf[p][0], bf[p][2]);
                mma_bf16(acc[0][2*p+1], af[0], bf[p][1], bf[p][3]);
                mma_bf16(acc[1][2*p+1], af[1], bf[p][1], bf[p][3]);
            }
        }
        __syncthreads();
    }

    if(OUT==1 || OUT==2){
        float* Hout = (OUT==1) ? g_H : g_H2;
        #pragma unroll
        for(int mi=0;mi<2;mi++){
            int r0 = m0 + wm + mi*16 + g;
            #pragma unroll
            for(int nj=0;nj<8;nj++){
                int cc = n0 + wn + nj*8 + 2*t;
                float bb0 = bias[cc], bb1 = bias[cc+1];
                float x0=gelu_fast(acc[mi][nj][0]+bb0), x1=gelu_fast(acc[mi][nj][1]+bb1);
                float x2=gelu_fast(acc[mi][nj][2]+bb0), x3=gelu_fast(acc[mi][nj][3]+bb1);
                *reinterpret_cast<float2*>(&Hout[(size_t)r0*Dv + cc])     = make_float2(x0,x1);
                *reinterpret_cast<float2*>(&Hout[(size_t)(r0+8)*Dv + cc]) = make_float2(x2,x3);
            }
        }
    }else if(OUT==3){
        #pragma unroll
        for(int mi=0;mi<2;mi++){
            int r0 = m0 + wm + mi*16 + g;
            #pragma unroll
            for(int nj=0;nj<8;nj++){
                int cc = n0 + wn + nj*8 + 2*t;
                *reinterpret_cast<uint32_t*>(&g_Ubf[(size_t)r0*Dv + cc])
                    = packbf(acc[mi][nj][0], acc[mi][nj][1]);
                *reinterpret_cast<uint32_t*>(&g_Ubf[(size_t)(r0+8)*Dv + cc])
                    = packbf(acc[mi][nj][2], acc[mi][nj][3]);
            }
        }
    }else{
        float cb = *cb_ptr;
        const float* msk = g_mask + b*Nv;
        const float* ct  = corr_t + (size_t)b*Nv*Nv;
        float local = 0.f;
        #pragma unroll
        for(int mi=0;mi<2;mi++){
            int r0 = wm + mi*16 + g;
            float mr0 = msk[r0], mr8 = msk[r0+8];
            #pragma unroll
            for(int nj=0;nj<8;nj++){
                int cc = wn + nj*8 + 2*t;
                float mc0 = msk[cc], mc1 = msk[cc+1];
                float2 t0 = *reinterpret_cast<const float2*>(&ct[(size_t)r0*Nv + cc]);
                float2 t1 = *reinterpret_cast<const float2*>(&ct[(size_t)(r0+8)*Nv + cc]);
                float s0 = (r0==cc)     ? 1.f : htanh(acc[mi][nj][0]+cb);
                float s1 = (r0==cc+1)   ? 1.f : htanh(acc[mi][nj][1]+cb);
                float s2 = (r0+8==cc)   ? 1.f : htanh(acc[mi][nj][2]+cb);
                float s3 = (r0+8==cc+1) ? 1.f : htanh(acc[mi][nj][3]+cb);
                float d0=s0-t0.x, d1=s1-t0.y, d2=s2-t1.x, d3=s3-t1.y;
                local += fmaxf(mr0,mc0)*d0*d0 + fmaxf(mr0,mc1)*d1*d1
                       + fmaxf(mr8,mc0)*d2*d2 + fmaxf(mr8,mc1)*d3*d3;
            }
        }
        #pragma unroll
        for(int o=16;o>0;o>>=1) local += __shfl_down_sync(0xffffffffu, local, o);
        if(lane==0) sm[wid] = local;
        __syncthreads();
        if(tid==0){
            float tot = 0.f;
            #pragma unroll
            for(int w=0;w<8;w++) tot += sm[w];
            g_part_c[b] = tot;
        }
    }
}

// fused big GEMM: grid (12, 256); bx>>2 selects weight slot / epilogue
__global__ void __launch_bounds__(256,2)
k_gemm_all(const float* __restrict__ tb1, const float* __restrict__ sb1){
    extern __shared__ float sm[];
    uint32_t sb = s2u(sm);
    int slot = blockIdx.x>>2;
    int n0 = (blockIdx.x&3)*128, m0 = blockIdx.y*128;
    const __nv_bfloat16* Ab = g_Ebf + (size_t)m0*Dv;
    const __nv_bfloat16* Bb = g_WTbf + (size_t)slot*Dv*Dv + (size_t)n0*Dv;
    if(slot==0)      gemm_body<1>(Ab, Bb, sm, sb, m0, n0, tb1, nullptr, nullptr, 0);
    else if(slot==1) gemm_body<2>(Ab, Bb, sm, sb, m0, n0, sb1, nullptr, nullptr, 0);
    else             gemm_body<3>(Ab, Bb, sm, sb, m0, n0, nullptr, nullptr, nullptr, 0);
}

__global__ void __launch_bounds__(256,2)
k_corr_bf(const float* __restrict__ corr_t, const float* __restrict__ cb_ptr){
    extern __shared__ float sm[];
    uint32_t sb = s2u(sm);
    int b = blockIdx.x;
    const __nv_bfloat16* Ab = g_Ubf + (size_t)b*Nv*Dv;
    const __nv_bfloat16* Bb = g_Ebf + (size_t)b*Nv*Dv;
    gemm_body<4>(Ab, Bb, sm, sb, 0, 0, nullptr, corr_t, cb_ptr, b);
}

// ---------------- warp-per-row heads ----------------
__global__ void __launch_bounds__(256) k_type(const float* __restrict__ W2,
                                              const float* __restrict__ b2,
                                              const float* __restrict__ gam,
                                              const float* __restrict__ bet,
                                              const int* __restrict__ tgt){
    int wid = threadIdx.x>>5, lane = threadIdx.x&31;
    int row = blockIdx.x*8 + wid;
    const float4* h4 = reinterpret_cast<const float4*>(g_H + (size_t)row*Dv);
    float4 x[4];
    #pragma unroll
    for(int i=0;i<4;i++) x[i] = h4[lane + 32*i];
    float s = 0.f;
    #pragma unroll
    for(int i=0;i<4;i++) s += x[i].x+x[i].y+x[i].z+x[i].w;
    float mu = warpAllSum(s) * (1.f/Dv);
    float vv = 0.f;
    #pragma unroll
    for(int i=0;i<4;i++){
        float a=x[i].x-mu,b=x[i].y-mu,c=x[i].z-mu,d=x[i].w-mu;
        vv += a*a+b*b+c*c+d*d;
    }
    float rs = rsqrtf(warpAllSum(vv)*(1.f/Dv) + 1e-5f);
    float p[6] = {0,0,0,0,0,0};
    #pragma unroll
    for(int i=0;i<4;i++){
        int r0 = lane*4 + 128*i;
        float4 g4 = reinterpret_cast<const float4*>(gam)[lane+32*i];
        float4 b4 = reinterpret_cast<const float4*>(bet)[lane+32*i];
        float y[4];
        y[0]=(x[i].x-mu)*rs*g4.x+b4.x; y[1]=(x[i].y-mu)*rs*g4.y+b4.y;
        y[2]=(x[i].z-mu)*rs*g4.z+b4.z; y[3]=(x[i].w-mu)*rs*g4.w+b4.w;
        float wf[24];
        const float4* w4 = reinterpret_cast<const float4*>(W2 + (size_t)r0*6);
        #pragma unroll
        for(int j=0;j<6;j++) reinterpret_cast<float4*>(wf)[j] = w4[j];
        #pragma unroll
        for(int r=0;r<4;r++)
            #pragma unroll
            for(int c=0;c<6;c++) p[c] = fmaf(y[r], wf[r*6+c], p[c]);
    }
    #pragma unroll
    for(int c=0;c<6;c++) p[c] = warpAllSum(p[c]);
    if(lane==0){
        float mx = -1e30f;
        #pragma unroll
        for(int c=0;c<6;c++){ p[c] += b2[c]; mx = fmaxf(mx, p[c]); }
        float se = 0.f;
        #pragma unroll
        for(int c=0;c<6;c++) se += expf(p[c]-mx);
        float lse = mx + logf(se);
        int tt = tgt[row & (Nv-1)];
        g_part_t[row] = g_mask[row] * (lse - p[tt]);
    }
}

__global__ void __launch_bounds__(256) k_stats(const float* __restrict__ W2,
                                               const float* __restrict__ b2,
                                               const float* __restrict__ gam,
                                               const float* __restrict__ bet,
                                               const float* __restrict__ st){
    int wid = threadIdx.x>>5, lane = threadIdx.x&31;
    int row = blockIdx.x*8 + wid;
    const float4* h4 = reinterpret_cast<const float4*>(g_H2 + (size_t)row*Dv);
    float4 x[4];
    #pragma unroll
    for(int i=0;i<4;i++) x[i] = h4[lane + 32*i];
    float s = 0.f;
    #pragma unroll
    for(int i=0;i<4;i++) s += x[i].x+x[i].y+x[i].z+x[i].w;
    float mu = warpAllSum(s) * (1.f/Dv);
    float vv = 0.f;
    #pragma unroll
    for(int i=0;i<4;i++){
        float a=x[i].x-mu,b=x[i].y-mu,c=x[i].z-mu,d=x[i].w-mu;
        vv += a*a+b*b+c*c+d*d;
    }
    float rs = rsqrtf(warpAllSum(vv)*(1.f/Dv) + 1e-5f);
    float p[8] = {0,0,0,0,0,0,0,0};
    #pragma unroll
    for(int i=0;i<4;i++){
        int r0 = lane*4 + 128*i;
        float4 g4 = reinterpret_cast<const float4*>(gam)[lane+32*i];
        float4 b4 = reinterpret_cast<const float4*>(bet)[lane+32*i];
        float y[4];
        y[0]=(x[i].x-mu)*rs*g4.x+b4.x; y[1]=(x[i].y-mu)*rs*g4.y+b4.y;
        y[2]=(x[i].z-mu)*rs*g4.z+b4.z; y[3]=(x[i].w-mu)*rs*g4.w+b4.w;
        float wf[32];
        const float4* w4 = reinterpret_cast<const float4*>(W2 + (size_t)r0*8);
        #pragma unroll
        for(int j=0;j<8;j++) reinterpret_cast<float4*>(wf)[j] = w4[j];
        #pragma unroll
        for(int r=0;r<4;r++)
            #pragma unroll
            for(int c=0;c<8;c++) p[c] = fmaf(y[r], wf[r*8+c], p[c]);
    }
    #pragma unroll
    for(int c=0;c<8;c++) p[c] = warpAllSum(p[c]);
    if(lane==0){
        float ssum = 0.f;
        #pragma unroll
        for(int c=0;c<8;c++){
            float d = p[c] + b2[c] - st[(size_t)row*8 + c];
            ssum += d*d;
        }
        g_part_s[row] = g_mask[row] * ssum;
    }
}

// ---------------- final deterministic combine ----------------
__global__ void k_final(float* __restrict__ out){
    __shared__ double sh[1024];
    int tid = threadIdx.x;
    double tsum=0, ssum=0, csum=0, nm=0, nme=0;
    for(int i=tid;i<BNv;i+=1024){ tsum += (double)g_part_t[i]; ssum += (double)g_part_s[i]; }
    for(int i=tid;i<Bv;i+=1024){
        csum += (double)g_part_c[i];
        double cnt = (double)g_cnt[i];
        nm += cnt;
        double u = (double)Nv - cnt;
        nme += (double)Nv*(double)Nv - u*u;
    }
    double vals[5] = {tsum, ssum, csum, nm, nme};
    for(int v=0;v<5;v++){
        sh[tid] = vals[v]; __syncthreads();
        for(int o=512;o>0;o>>=1){ if(tid<o) sh[tid]+=sh[tid+o]; __syncthreads(); }
        vals[v] = sh[0]; __syncthreads();
    }
    if(tid==0){
        double nm_  = vals[3] < 1.0 ? 1.0 : vals[3];
        double nme_ = vals[4] < 1.0 ? 1.0 : vals[4];
        double total = vals[0]/nm_ + vals[1]/(nm_*8.0) + 0.5*vals[2]/nme_;
        out[0] = (float)total;
    }
}

// ---------------- launch ----------------
extern "C" void kernel_launch(void* const* d_in, const int* in_sizes, int n_in,
                              void* d_out, int out_size){
    const float* e     = (const float*)d_in[0];
    const void*  mraw  = d_in[1];
    const int*   tgt   = (const int*)d_in[2];
    const float* stats = (const float*)d_in[3];
    const float* corr  = (const float*)d_in[4];
    const float* tW1  = (const float*)d_in[5];
    const float* tb1  = (const float*)d_in[6];
    const float* tg   = (const float*)d_in[7];
    const float* tbe  = (const float*)d_in[8];
    const float* tW2  = (const float*)d_in[9];
    const float* tb2  = (const float*)d_in[10];
    const float* sW1  = (const float*)d_in[11];
    const float* sb1  = (const float*)d_in[12];
    const float* sg   = (const float*)d_in[13];
    const float* sbe  = (const float*)d_in[14];
    const float* sW2  = (const float*)d_in[15];
    const float* sb2  = (const float*)d_in[16];
    const float* cW   = (const float*)d_in[17];
    const float* cb   = (const float*)d_in[18];

    static int s_init = 0;
    if(!s_init){
        cudaFuncSetAttribute(k_gemm_all, cudaFuncAttributeMaxDynamicSharedMemorySize, SMEM_SZ);
        cudaFuncSetAttribute(k_corr_bf,  cudaFuncAttributeMaxDynamicSharedMemorySize, SMEM_SZ);
        s_init = 1;
    }

    k_detect<<<1,256>>>((const unsigned int*)mraw);
    k_expand_mask<<<BNv/256,256>>>(mraw);
    k_cnt<<<Bv,128>>>();
    k_cvt<<<(BNv*(Dv/4))/256,256>>>(e);

    dim3 tg3(16,16,3), tb_(32,8);
    k_transpose3<<<tg3,tb_>>>(tW1, sW1, cW);

    dim3 gg(12, BNv/128);   // fused: 3 weight slots x 4 n-tiles, 256 m-tiles
    k_gemm_all<<<gg,256,SMEM_SZ>>>(tb1, sb1);

    k_type <<<BNv/8,256>>>(tW2, tb2, tg, tbe, tgt);
    k_stats<<<BNv/8,256>>>(sW2, sb2, sg, sbe, stats);
    k_corr_bf<<<Bv,256,SMEM_SZ>>>(corr, cb);

    k_final<<<1,1024>>>((float*)d_out);
}